// round 1
// baseline (speedup 1.0000x reference)
#include <cuda_runtime.h>
#include <math.h>

// Problem constants (match reference_code)
#define NN   50000
#define EE   400000
#define F_IN 128
#define HH   3
#define DD   64
#define HD   192   // H*D
#define GG   64
#define PP   64
#define NEG_GAT 0.2f
#define NEG  0.01f

// ---------------- device scratch (allocation-free rule: __device__ globals) ----
__device__ float g_fs[(size_t)NN * HD];     // fc_src features  [N,H,D]
__device__ float g_fd[(size_t)NN * HD];     // fc_dst features  [N,H,D]
__device__ float g_out[(size_t)NN * HD];    // layer output (init = bias) [N,H,D]
__device__ float g_ex[(size_t)EE * HH];     // exp(logits) per edge/head
__device__ float g_denom[(size_t)NN * HH];  // softmax denominators
__device__ float g_pool[GG * DD];           // per-graph sums
__device__ float g_cnt[GG];                 // per-graph node counts

// ---------------- SGEMM: C[M,192] = A[M,K] @ W[K,192] ---------------------------
// BM=128, BN=64, BK=16, 256 threads, 8x4 micro-tile
#define BM 128
#define BN 64
#define BK 16

__global__ void sgemm_kernel(const float* __restrict__ Xext,
                             const float* __restrict__ W,
                             int K, int use_internal_x, int out_sel) {
    const float* __restrict__ A = use_internal_x ? g_out : Xext;
    float* __restrict__ C = out_sel ? g_fd : g_fs;
    const int M = NN;
    const int NC = HD;

    __shared__ float As[BK][BM];
    __shared__ float Bs[BK][BN];

    int tid  = threadIdx.x;
    int row0 = blockIdx.x * BM;
    int col0 = blockIdx.y * BN;

    int tr = (tid >> 4) << 3;   // 0..120 step 8
    int tc = (tid & 15) << 2;   // 0..60  step 4

    float acc[8][4];
#pragma unroll
    for (int i = 0; i < 8; i++)
#pragma unroll
        for (int j = 0; j < 4; j++) acc[i][j] = 0.f;

    int arow = tid >> 2;          // 0..63 (+64 for second load)
    int acol = (tid & 3) << 2;    // 0,4,8,12
    int brow = tid >> 4;          // 0..15
    int bcol = (tid & 15) << 2;   // 0..60

    for (int k0 = 0; k0 < K; k0 += BK) {
#pragma unroll
        for (int t = 0; t < 2; t++) {
            int r  = arow + t * 64;
            int gr = row0 + r;
            float4 av = make_float4(0.f, 0.f, 0.f, 0.f);
            if (gr < M)
                av = *reinterpret_cast<const float4*>(A + (size_t)gr * K + k0 + acol);
            As[acol + 0][r] = av.x;
            As[acol + 1][r] = av.y;
            As[acol + 2][r] = av.z;
            As[acol + 3][r] = av.w;
        }
        float4 bv = *reinterpret_cast<const float4*>(
            W + (size_t)(k0 + brow) * NC + col0 + bcol);
        *reinterpret_cast<float4*>(&Bs[brow][bcol]) = bv;
        __syncthreads();

#pragma unroll
        for (int k = 0; k < BK; k++) {
            float4 b0 = *reinterpret_cast<const float4*>(&Bs[k][tc]);
            float4 a0 = *reinterpret_cast<const float4*>(&As[k][tr]);
            float4 a1 = *reinterpret_cast<const float4*>(&As[k][tr + 4]);
            float ar[8] = {a0.x, a0.y, a0.z, a0.w, a1.x, a1.y, a1.z, a1.w};
            float br[4] = {b0.x, b0.y, b0.z, b0.w};
#pragma unroll
            for (int i = 0; i < 8; i++)
#pragma unroll
                for (int j = 0; j < 4; j++) acc[i][j] += ar[i] * br[j];
        }
        __syncthreads();
    }

#pragma unroll
    for (int i = 0; i < 8; i++) {
        int gr = row0 + tr + i;
        if (gr < M) {
            float4 cv = make_float4(acc[i][0], acc[i][1], acc[i][2], acc[i][3]);
            *reinterpret_cast<float4*>(C + (size_t)gr * NC + col0 + tc) = cv;
        }
    }
}

// ---------------- per-layer init: out = bias (fused bias add), denom = 0 --------
__global__ void init_layer_kernel(const float* __restrict__ bias) {
    int i = blockIdx.x * blockDim.x + threadIdx.x;
    if (i < NN * HD) g_out[i] = bias[i % HD];
    if (i < NN * HH) g_denom[i] = 0.f;
}

// ---------------- edge pass A: ex = exp(a . lrelu(fs[src]+fd[dst])), denom += ex
// one warp per edge; 48 float4 chunks per edge (192 floats)
__global__ void edge_pass_a(const int* __restrict__ src, const int* __restrict__ dst,
                            const float* __restrict__ attn) {
    int e = (blockIdx.x * blockDim.x + threadIdx.x) >> 5;
    if (e >= EE) return;
    int lane = threadIdx.x & 31;
    int s = src[e], d = dst[e];
    const float4* fs4 = reinterpret_cast<const float4*>(g_fs + (size_t)s * HD);
    const float4* fd4 = reinterpret_cast<const float4*>(g_fd + (size_t)d * HD);
    const float4* a4  = reinterpret_cast<const float4*>(attn);

    float p0 = 0.f, p1 = 0.f, p2 = 0.f;
    {   // chunk f = lane (heads 0/1)
        float4 u = fs4[lane], v = fd4[lane], a = a4[lane];
        float x0 = u.x + v.x, x1 = u.y + v.y, x2 = u.z + v.z, x3 = u.w + v.w;
        x0 = x0 > 0.f ? x0 : NEG_GAT * x0;
        x1 = x1 > 0.f ? x1 : NEG_GAT * x1;
        x2 = x2 > 0.f ? x2 : NEG_GAT * x2;
        x3 = x3 > 0.f ? x3 : NEG_GAT * x3;
        float dv = x0 * a.x + x1 * a.y + x2 * a.z + x3 * a.w;
        if (lane < 16) p0 += dv; else p1 += dv;
    }
    if (lane < 16) {  // chunk f = lane + 32 (head 2)
        int f = lane + 32;
        float4 u = fs4[f], v = fd4[f], a = a4[f];
        float x0 = u.x + v.x, x1 = u.y + v.y, x2 = u.z + v.z, x3 = u.w + v.w;
        x0 = x0 > 0.f ? x0 : NEG_GAT * x0;
        x1 = x1 > 0.f ? x1 : NEG_GAT * x1;
        x2 = x2 > 0.f ? x2 : NEG_GAT * x2;
        x3 = x3 > 0.f ? x3 : NEG_GAT * x3;
        p2 += x0 * a.x + x1 * a.y + x2 * a.z + x3 * a.w;
    }
#pragma unroll
    for (int o = 16; o; o >>= 1) {
        p0 += __shfl_xor_sync(0xffffffffu, p0, o);
        p1 += __shfl_xor_sync(0xffffffffu, p1, o);
        p2 += __shfl_xor_sync(0xffffffffu, p2, o);
    }
    if (lane < 3) {
        float l = (lane == 0) ? p0 : (lane == 1 ? p1 : p2);
        float ev = expf(l);                       // max-subtraction is a no-op for alpha
        g_ex[(size_t)e * 3 + lane] = ev;
        atomicAdd(&g_denom[(size_t)d * 3 + lane], ev);
    }
}

// ---------------- edge pass B: out[dst] += (ex/denom) * fs[src] -----------------
__global__ void edge_pass_b(const int* __restrict__ src, const int* __restrict__ dst) {
    int e = (blockIdx.x * blockDim.x + threadIdx.x) >> 5;
    if (e >= EE) return;
    int lane = threadIdx.x & 31;
    int s = src[e], d = dst[e];
    float al[3];
#pragma unroll
    for (int h = 0; h < 3; h++) {
        float dn = g_denom[(size_t)d * 3 + h];
        al[h] = g_ex[(size_t)e * 3 + h] / fmaxf(dn, 1e-9f);
    }
    const float4* fs4 = reinterpret_cast<const float4*>(g_fs + (size_t)s * HD);
    float* outr = g_out + (size_t)d * HD;
    {
        int f = lane;
        float4 u = fs4[f];
        float a = al[f >> 4];
        int base = f << 2;
        atomicAdd(&outr[base + 0], u.x * a);
        atomicAdd(&outr[base + 1], u.y * a);
        atomicAdd(&outr[base + 2], u.z * a);
        atomicAdd(&outr[base + 3], u.w * a);
    }
    if (lane < 16) {
        int f = lane + 32;
        float4 u = fs4[f];
        float a = al[2];
        int base = f << 2;
        atomicAdd(&outr[base + 0], u.x * a);
        atomicAdd(&outr[base + 1], u.y * a);
        atomicAdd(&outr[base + 2], u.z * a);
        atomicAdd(&outr[base + 3], u.w * a);
    }
}

// ---------------- graph pooling ---------------------------------------------------
__global__ void pool_zero_kernel() {
    int i = blockIdx.x * blockDim.x + threadIdx.x;
    if (i < GG * DD) g_pool[i] = 0.f;
    if (i < GG) g_cnt[i] = 0.f;
}

__global__ void pool_kernel(const int* __restrict__ gid) {
    int i = blockIdx.x * blockDim.x + threadIdx.x;
    if (i >= NN * DD) return;
    int n = i >> 6, d = i & 63;
    int g = gid[n];
    const float* r = g_out + (size_t)n * HD;
    float v = (r[d] + r[64 + d] + r[128 + d]) * (1.f / 3.f);
    atomicAdd(&g_pool[g * DD + d], v);
    if (d == 0) atomicAdd(&g_cnt[g], 1.f);
}

// ---------------- pattern branch + classifier head (single block) -----------------
__global__ void head_kernel(const float* __restrict__ p1, const float* __restrict__ p2,
                            const float* __restrict__ p3,
                            const float* __restrict__ Wex, const float* __restrict__ bex,
                            const float* __restrict__ Wpat, const float* __restrict__ bpat,
                            const float* __restrict__ Wc1, const float* __restrict__ bc1,
                            const float* __restrict__ Wc2, const float* __restrict__ bc2,
                            const float* __restrict__ Wc3, const float* __restrict__ bc3,
                            float* __restrict__ outp) {
    __shared__ float s_px[GG * 96];   // reused: px -> c1 (first 4096) + c2 (next 2048)
    __shared__ float s_pat[GG * 64];
    int tid = threadIdx.x;

    // stage 1: px = [p1@Wex+bex | p2@Wex+bex | p3@Wex+bex]   (no activation)
    for (int idx = tid; idx < GG * 96; idx += 256) {
        int g = idx / 96, j = idx % 96;
        const float* p = (j < 32) ? p1 : (j < 64 ? p2 : p3);
        int jj = j & 31;
        float s = bex[jj];
        for (int k = 0; k < PP; k++) s += p[g * PP + k] * Wex[k * 32 + jj];
        s_px[idx] = s;
    }
    __syncthreads();

    // stage 2: pat = lrelu(px @ Wpat + bpat, 0.01)
    for (int idx = tid; idx < GG * 64; idx += 256) {
        int g = idx >> 6, j = idx & 63;
        float s = bpat[j];
        for (int k = 0; k < 96; k++) s += s_px[g * 96 + k] * Wpat[k * 64 + j];
        s_pat[idx] = s > 0.f ? s : NEG * s;
    }
    __syncthreads();

    // stage 3: c1 = lrelu([gnn_out | pat] @ Wc1 + bc1)  -> into s_px[0..4095]
    for (int idx = tid; idx < GG * 64; idx += 256) {
        int g = idx >> 6, j = idx & 63;
        float s = bc1[j];
        float inv = 1.f / fmaxf(g_cnt[g], 1.f);
        for (int k = 0; k < 64; k++) s += (g_pool[g * 64 + k] * inv) * Wc1[k * 64 + j];
        for (int k = 0; k < 64; k++) s += s_pat[g * 64 + k] * Wc1[(64 + k) * 64 + j];
        s_px[idx] = s > 0.f ? s : NEG * s;
    }
    __syncthreads();

    // stage 4: c2 = lrelu(c1 @ Wc2 + bc2) -> into s_px[4096..6143]
    for (int idx = tid; idx < GG * 32; idx += 256) {
        int g = idx >> 5, j = idx & 31;
        float s = bc2[j];
        for (int k = 0; k < 64; k++) s += s_px[g * 64 + k] * Wc2[k * 32 + j];
        s_px[4096 + idx] = s > 0.f ? s : NEG * s;
    }
    __syncthreads();

    // stage 5: out = c2 @ Wc3 + bc3
    for (int idx = tid; idx < GG * 2; idx += 256) {
        int g = idx >> 1, j = idx & 1;
        float s = bc3[j];
        for (int k = 0; k < 32; k++) s += s_px[4096 + g * 32 + k] * Wc3[k * 2 + j];
        outp[idx] = s;
    }
}

// ---------------- launcher ---------------------------------------------------------
extern "C" void kernel_launch(void* const* d_in, const int* in_sizes, int n_in,
                              void* d_out, int out_size) {
    const float* x_in = (const float*)d_in[0];
    const int*   src  = (const int*)d_in[1];
    const int*   dst  = (const int*)d_in[2];
    const int*   gid  = (const int*)d_in[3];
    const float* p1   = (const float*)d_in[4];
    const float* p2   = (const float*)d_in[5];
    const float* p3   = (const float*)d_in[6];
    const float* W1s = (const float*)d_in[7],  *W1d = (const float*)d_in[8];
    const float* a1  = (const float*)d_in[9],  *b1  = (const float*)d_in[10];
    const float* W2s = (const float*)d_in[11], *W2d = (const float*)d_in[12];
    const float* a2  = (const float*)d_in[13], *b2  = (const float*)d_in[14];
    const float* W3s = (const float*)d_in[15], *W3d = (const float*)d_in[16];
    const float* a3  = (const float*)d_in[17], *b3  = (const float*)d_in[18];
    const float* Wex = (const float*)d_in[19], *bex = (const float*)d_in[20];
    const float* Wpat= (const float*)d_in[21], *bpat= (const float*)d_in[22];
    const float* Wc1 = (const float*)d_in[23], *bc1 = (const float*)d_in[24];
    const float* Wc2 = (const float*)d_in[25], *bc2 = (const float*)d_in[26];
    const float* Wc3 = (const float*)d_in[27], *bc3 = (const float*)d_in[28];

    dim3 gemm_grid((NN + BM - 1) / BM, HD / BN);   // (391, 3)
    int  init_blocks = (NN * HD + 255) / 256;       // 37500
    int  edge_blocks = (EE * 32 + 255) / 256;       // 50000
    int  pool_blocks = (NN * DD + 255) / 256;       // 12500

    // ---- Layer 1 (K = F_IN = 128, X = inputs)
    sgemm_kernel<<<gemm_grid, 256>>>(x_in, W1s, F_IN, 0, 0);
    sgemm_kernel<<<gemm_grid, 256>>>(x_in, W1d, F_IN, 0, 1);
    init_layer_kernel<<<init_blocks, 256>>>(b1);
    edge_pass_a<<<edge_blocks, 256>>>(src, dst, a1);
    edge_pass_b<<<edge_blocks, 256>>>(src, dst);

    // ---- Layer 2 (K = HD = 192, X = g_out)
    sgemm_kernel<<<gemm_grid, 256>>>(nullptr, W2s, HD, 1, 0);
    sgemm_kernel<<<gemm_grid, 256>>>(nullptr, W2d, HD, 1, 1);
    init_layer_kernel<<<init_blocks, 256>>>(b2);
    edge_pass_a<<<edge_blocks, 256>>>(src, dst, a2);
    edge_pass_b<<<edge_blocks, 256>>>(src, dst);

    // ---- Layer 3
    sgemm_kernel<<<gemm_grid, 256>>>(nullptr, W3s, HD, 1, 0);
    sgemm_kernel<<<gemm_grid, 256>>>(nullptr, W3d, HD, 1, 1);
    init_layer_kernel<<<init_blocks, 256>>>(b3);
    edge_pass_a<<<edge_blocks, 256>>>(src, dst, a3);
    edge_pass_b<<<edge_blocks, 256>>>(src, dst);

    // ---- pooling + head
    pool_zero_kernel<<<17, 256>>>();
    pool_kernel<<<pool_blocks, 256>>>(gid);
    head_kernel<<<1, 256>>>(p1, p2, p3, Wex, bex, Wpat, bpat,
                            Wc1, bc1, Wc2, bc2, Wc3, bc3, (float*)d_out);
}

// round 2
// speedup vs baseline: 1.3095x; 1.3095x over previous
#include <cuda_runtime.h>
#include <math.h>

// Problem constants (match reference_code)
#define NN   50000
#define EE   400000
#define F_IN 128
#define HH   3
#define DD   64
#define HD   192   // H*D
#define GG   64
#define PP   64
#define NEG_GAT 0.2f
#define NEG  0.01f

// ---------------- device scratch (allocation-free rule: __device__ globals) ----
__device__ __align__(16) float g_fs[(size_t)NN * HD];     // fc_src features  [N,H,D]
__device__ __align__(16) float g_fd[(size_t)NN * HD];     // fc_dst features  [N,H,D]
__device__ __align__(16) float g_out[(size_t)NN * HD];    // layer output (init = bias) [N,H,D]
__device__ __align__(16) float g_ex[(size_t)EE * HH];     // exp(logits) per edge/head
__device__ __align__(16) float g_denom[(size_t)NN * HH];  // softmax denominators
__device__ __align__(16) float g_pool[GG * DD];           // per-graph sums
__device__ float g_cnt[GG];                               // per-graph node counts

// ---------------- Fused SGEMM: [g_fs | g_fd] = A[M,K] @ [Ws | Wd]  (N = 384) ----
// BM=128, BN=128, BK=16, 256 threads, 8x8 micro-tile, register prefetch pipeline
#define BM 128
#define BN 128
#define BK 16

__global__ __launch_bounds__(256) void sgemm_fused_kernel(
        const float* __restrict__ Xext,
        const float* __restrict__ Ws,
        const float* __restrict__ Wd,
        int K, int use_internal_x) {
    const float* __restrict__ A = use_internal_x ? g_out : Xext;

    __shared__ float As[BK][BM];   // transposed A tile
    __shared__ float Bs[BK][BN];

    const int tid  = threadIdx.x;
    const int row0 = blockIdx.x * BM;
    const int col0 = blockIdx.y * BN;   // 0,128,256 over N=384

    const int ty4 = (tid >> 4) << 2;    // 0..60 step 4
    const int tx4 = (tid & 15) << 2;    // 0..60 step 4

    // A-tile load indices
    const int arow  = tid >> 1;         // 0..127
    const int acol8 = (tid & 1) << 3;   // 0 or 8
    // B-tile load indices
    const int brow  = tid >> 4;         // 0..15
    const int bcol4 = (tid & 15) << 2;  // 0..60

    float acc[8][8];
#pragma unroll
    for (int i = 0; i < 8; i++)
#pragma unroll
        for (int j = 0; j < 8; j++) acc[i][j] = 0.f;

    const int nk = K / BK;

    // ---- prefetch tile 0 into registers
    float4 pa0, pa1, pb0, pb1;
    {
        int gr = row0 + arow;
        pa0 = make_float4(0.f, 0.f, 0.f, 0.f);
        pa1 = pa0;
        if (gr < NN) {
            pa0 = *reinterpret_cast<const float4*>(A + (size_t)gr * K + acol8);
            pa1 = *reinterpret_cast<const float4*>(A + (size_t)gr * K + acol8 + 4);
        }
        int cg0 = col0 + bcol4;
        int cg1 = cg0 + 64;
        pb0 = (cg0 < HD)
            ? *reinterpret_cast<const float4*>(Ws + (size_t)brow * HD + cg0)
            : *reinterpret_cast<const float4*>(Wd + (size_t)brow * HD + (cg0 - HD));
        pb1 = (cg1 < HD)
            ? *reinterpret_cast<const float4*>(Ws + (size_t)brow * HD + cg1)
            : *reinterpret_cast<const float4*>(Wd + (size_t)brow * HD + (cg1 - HD));
    }

    for (int t = 0; t < nk; t++) {
        __syncthreads();
        // store prefetched tile into smem
        As[acol8 + 0][arow] = pa0.x;
        As[acol8 + 1][arow] = pa0.y;
        As[acol8 + 2][arow] = pa0.z;
        As[acol8 + 3][arow] = pa0.w;
        As[acol8 + 4][arow] = pa1.x;
        As[acol8 + 5][arow] = pa1.y;
        As[acol8 + 6][arow] = pa1.z;
        As[acol8 + 7][arow] = pa1.w;
        *reinterpret_cast<float4*>(&Bs[brow][bcol4])      = pb0;
        *reinterpret_cast<float4*>(&Bs[brow][bcol4 + 64]) = pb1;
        __syncthreads();

        // prefetch next tile
        if (t + 1 < nk) {
            int k0 = (t + 1) * BK;
            int gr = row0 + arow;
            pa0 = make_float4(0.f, 0.f, 0.f, 0.f);
            pa1 = pa0;
            if (gr < NN) {
                pa0 = *reinterpret_cast<const float4*>(A + (size_t)gr * K + k0 + acol8);
                pa1 = *reinterpret_cast<const float4*>(A + (size_t)gr * K + k0 + acol8 + 4);
            }
            int cg0 = col0 + bcol4;
            int cg1 = cg0 + 64;
            pb0 = (cg0 < HD)
                ? *reinterpret_cast<const float4*>(Ws + (size_t)(k0 + brow) * HD + cg0)
                : *reinterpret_cast<const float4*>(Wd + (size_t)(k0 + brow) * HD + (cg0 - HD));
            pb1 = (cg1 < HD)
                ? *reinterpret_cast<const float4*>(Ws + (size_t)(k0 + brow) * HD + cg1)
                : *reinterpret_cast<const float4*>(Wd + (size_t)(k0 + brow) * HD + (cg1 - HD));
        }

        // compute on current tile
#pragma unroll
        for (int k = 0; k < BK; k++) {
            float4 a0 = *reinterpret_cast<const float4*>(&As[k][ty4]);
            float4 a1 = *reinterpret_cast<const float4*>(&As[k][ty4 + 64]);
            float4 b0 = *reinterpret_cast<const float4*>(&Bs[k][tx4]);
            float4 b1 = *reinterpret_cast<const float4*>(&Bs[k][tx4 + 64]);
            float ar[8] = {a0.x, a0.y, a0.z, a0.w, a1.x, a1.y, a1.z, a1.w};
            float br[8] = {b0.x, b0.y, b0.z, b0.w, b1.x, b1.y, b1.z, b1.w};
#pragma unroll
            for (int i = 0; i < 8; i++)
#pragma unroll
                for (int j = 0; j < 8; j++) acc[i][j] += ar[i] * br[j];
        }
    }

    // write out: columns [0,192) -> g_fs, [192,384) -> g_fd
#pragma unroll
    for (int i = 0; i < 8; i++) {
        int row = row0 + ty4 + (i & 3) + ((i >> 2) << 6);
        if (row >= NN) continue;
        int cg0 = col0 + tx4;
        int cg1 = cg0 + 64;
        float4 v0 = make_float4(acc[i][0], acc[i][1], acc[i][2], acc[i][3]);
        float4 v1 = make_float4(acc[i][4], acc[i][5], acc[i][6], acc[i][7]);
        if (cg0 < HD)
            *reinterpret_cast<float4*>(g_fs + (size_t)row * HD + cg0) = v0;
        else
            *reinterpret_cast<float4*>(g_fd + (size_t)row * HD + (cg0 - HD)) = v0;
        if (cg1 < HD)
            *reinterpret_cast<float4*>(g_fs + (size_t)row * HD + cg1) = v1;
        else
            *reinterpret_cast<float4*>(g_fd + (size_t)row * HD + (cg1 - HD)) = v1;
    }
}

// ---------------- per-layer init: out = bias (fused bias add), denom = 0 --------
__global__ void init_layer_kernel(const float* __restrict__ bias) {
    int i = blockIdx.x * blockDim.x + threadIdx.x;
    if (i < NN * HD) g_out[i] = bias[i % HD];
    if (i < NN * HH) g_denom[i] = 0.f;
}

// ---------------- edge pass A: ex = exp(a . lrelu(fs[src]+fd[dst])), denom += ex
// 16 lanes per edge (2 edges per warp); 3 float4 chunks per lane
__global__ void edge_pass_a(const int* __restrict__ src, const int* __restrict__ dst,
                            const float* __restrict__ attn) {
    int gt = blockIdx.x * blockDim.x + threadIdx.x;
    int e = gt >> 4;
    if (e >= EE) return;
    int l16 = threadIdx.x & 15;
    int s = src[e], d = dst[e];
    const float4* fs4 = reinterpret_cast<const float4*>(g_fs + (size_t)s * HD);
    const float4* fd4 = reinterpret_cast<const float4*>(g_fd + (size_t)d * HD);
    const float4* a4  = reinterpret_cast<const float4*>(attn);

    float p[3];
#pragma unroll
    for (int h = 0; h < 3; h++) {
        int f = (h << 4) + l16;
        float4 u = fs4[f], v = fd4[f], a = a4[f];
        float x0 = u.x + v.x, x1 = u.y + v.y, x2 = u.z + v.z, x3 = u.w + v.w;
        x0 = x0 > 0.f ? x0 : NEG_GAT * x0;
        x1 = x1 > 0.f ? x1 : NEG_GAT * x1;
        x2 = x2 > 0.f ? x2 : NEG_GAT * x2;
        x3 = x3 > 0.f ? x3 : NEG_GAT * x3;
        p[h] = x0 * a.x + x1 * a.y + x2 * a.z + x3 * a.w;
    }
#pragma unroll
    for (int o = 8; o; o >>= 1) {
        p[0] += __shfl_xor_sync(0xffffffffu, p[0], o);
        p[1] += __shfl_xor_sync(0xffffffffu, p[1], o);
        p[2] += __shfl_xor_sync(0xffffffffu, p[2], o);
    }
    if (l16 < 3) {
        float ev = expf(p[l16]);             // max-subtraction is a no-op for alpha
        g_ex[(size_t)e * 3 + l16] = ev;
        atomicAdd(&g_denom[(size_t)d * 3 + l16], ev);
    }
}

// ---------------- edge pass B: out[dst] += (ex/denom) * fs[src] -----------------
// 16 lanes per edge; vector red.global.add.v4.f32
__global__ void edge_pass_b(const int* __restrict__ src, const int* __restrict__ dst) {
    int gt = blockIdx.x * blockDim.x + threadIdx.x;
    int e = gt >> 4;
    if (e >= EE) return;
    int lane = threadIdx.x & 31;
    int l16 = lane & 15;
    int s = src[e], d = dst[e];

    float al_mine = 0.f;
    if (l16 < 3) {
        float dn = g_denom[(size_t)d * 3 + l16];
        al_mine = g_ex[(size_t)e * 3 + l16] / fmaxf(dn, 1e-9f);
    }
    float al[3];
#pragma unroll
    for (int h = 0; h < 3; h++)
        al[h] = __shfl_sync(0xffffffffu, al_mine, (lane & 16) + h);

    const float4* fs4 = reinterpret_cast<const float4*>(g_fs + (size_t)s * HD);
    float* outr = g_out + (size_t)d * HD;
#pragma unroll
    for (int h = 0; h < 3; h++) {
        int f = (h << 4) + l16;
        float4 u = fs4[f];
        float a = al[h];
        float x = u.x * a, y = u.y * a, z = u.z * a, w = u.w * a;
        asm volatile("red.global.add.v4.f32 [%0], {%1, %2, %3, %4};"
                     :: "l"(outr + (f << 2)), "f"(x), "f"(y), "f"(z), "f"(w)
                     : "memory");
    }
}

// ---------------- graph pooling ---------------------------------------------------
__global__ void pool_zero_kernel() {
    int i = blockIdx.x * blockDim.x + threadIdx.x;
    if (i < GG * DD) g_pool[i] = 0.f;
    if (i < GG) g_cnt[i] = 0.f;
}

__global__ void pool_kernel(const int* __restrict__ gid) {
    int i = blockIdx.x * blockDim.x + threadIdx.x;
    if (i >= NN * DD) return;
    int n = i >> 6, d = i & 63;
    int g = gid[n];
    const float* r = g_out + (size_t)n * HD;
    float v = (r[d] + r[64 + d] + r[128 + d]) * (1.f / 3.f);
    atomicAdd(&g_pool[g * DD + d], v);
    if (d == 0) atomicAdd(&g_cnt[g], 1.f);
}

// ---------------- pattern branch + classifier head (single block) -----------------
__global__ void head_kernel(const float* __restrict__ p1, const float* __restrict__ p2,
                            const float* __restrict__ p3,
                            const float* __restrict__ Wex, const float* __restrict__ bex,
                            const float* __restrict__ Wpat, const float* __restrict__ bpat,
                            const float* __restrict__ Wc1, const float* __restrict__ bc1,
                            const float* __restrict__ Wc2, const float* __restrict__ bc2,
                            const float* __restrict__ Wc3, const float* __restrict__ bc3,
                            float* __restrict__ outp) {
    __shared__ float s_px[GG * 96];   // reused: px -> c1 (first 4096) + c2 (next 2048)
    __shared__ float s_pat[GG * 64];
    int tid = threadIdx.x;

    // stage 1: px = [p1@Wex+bex | p2@Wex+bex | p3@Wex+bex]
    for (int idx = tid; idx < GG * 96; idx += 256) {
        int g = idx / 96, j = idx % 96;
        const float* p = (j < 32) ? p1 : (j < 64 ? p2 : p3);
        int jj = j & 31;
        float s = bex[jj];
        for (int k = 0; k < PP; k++) s += p[g * PP + k] * Wex[k * 32 + jj];
        s_px[idx] = s;
    }
    __syncthreads();

    // stage 2: pat = lrelu(px @ Wpat + bpat, 0.01)
    for (int idx = tid; idx < GG * 64; idx += 256) {
        int g = idx >> 6, j = idx & 63;
        float s = bpat[j];
        for (int k = 0; k < 96; k++) s += s_px[g * 96 + k] * Wpat[k * 64 + j];
        s_pat[idx] = s > 0.f ? s : NEG * s;
    }
    __syncthreads();

    // stage 3: c1 = lrelu([gnn_out | pat] @ Wc1 + bc1)  -> into s_px[0..4095]
    for (int idx = tid; idx < GG * 64; idx += 256) {
        int g = idx >> 6, j = idx & 63;
        float s = bc1[j];
        float inv = 1.f / fmaxf(g_cnt[g], 1.f);
        for (int k = 0; k < 64; k++) s += (g_pool[g * 64 + k] * inv) * Wc1[k * 64 + j];
        for (int k = 0; k < 64; k++) s += s_pat[g * 64 + k] * Wc1[(64 + k) * 64 + j];
        s_px[idx] = s > 0.f ? s : NEG * s;
    }
    __syncthreads();

    // stage 4: c2 = lrelu(c1 @ Wc2 + bc2) -> into s_px[4096..6143]
    for (int idx = tid; idx < GG * 32; idx += 256) {
        int g = idx >> 5, j = idx & 31;
        float s = bc2[j];
        for (int k = 0; k < 64; k++) s += s_px[g * 64 + k] * Wc2[k * 32 + j];
        s_px[4096 + idx] = s > 0.f ? s : NEG * s;
    }
    __syncthreads();

    // stage 5: out = c2 @ Wc3 + bc3
    for (int idx = tid; idx < GG * 2; idx += 256) {
        int g = idx >> 1, j = idx & 1;
        float s = bc3[j];
        for (int k = 0; k < 32; k++) s += s_px[4096 + g * 32 + k] * Wc3[k * 2 + j];
        outp[idx] = s;
    }
}

// ---------------- launcher ---------------------------------------------------------
extern "C" void kernel_launch(void* const* d_in, const int* in_sizes, int n_in,
                              void* d_out, int out_size) {
    const float* x_in = (const float*)d_in[0];
    const int*   src  = (const int*)d_in[1];
    const int*   dst  = (const int*)d_in[2];
    const int*   gid  = (const int*)d_in[3];
    const float* p1   = (const float*)d_in[4];
    const float* p2   = (const float*)d_in[5];
    const float* p3   = (const float*)d_in[6];
    const float* W1s = (const float*)d_in[7],  *W1d = (const float*)d_in[8];
    const float* a1  = (const float*)d_in[9],  *b1  = (const float*)d_in[10];
    const float* W2s = (const float*)d_in[11], *W2d = (const float*)d_in[12];
    const float* a2  = (const float*)d_in[13], *b2  = (const float*)d_in[14];
    const float* W3s = (const float*)d_in[15], *W3d = (const float*)d_in[16];
    const float* a3  = (const float*)d_in[17], *b3  = (const float*)d_in[18];
    const float* Wex = (const float*)d_in[19], *bex = (const float*)d_in[20];
    const float* Wpat= (const float*)d_in[21], *bpat= (const float*)d_in[22];
    const float* Wc1 = (const float*)d_in[23], *bc1 = (const float*)d_in[24];
    const float* Wc2 = (const float*)d_in[25], *bc2 = (const float*)d_in[26];
    const float* Wc3 = (const float*)d_in[27], *bc3 = (const float*)d_in[28];

    dim3 gemm_grid((NN + BM - 1) / BM, (2 * HD) / BN);   // (391, 3)
    int  init_blocks = (NN * HD + 255) / 256;            // 37500
    int  edge_blocks = (EE * 16 + 255) / 256;            // 25000
    int  pool_blocks = (NN * DD + 255) / 256;            // 12500

    // ---- Layer 1 (K = F_IN = 128, X = inputs)
    sgemm_fused_kernel<<<gemm_grid, 256>>>(x_in, W1s, W1d, F_IN, 0);
    init_layer_kernel<<<init_blocks, 256>>>(b1);
    edge_pass_a<<<edge_blocks, 256>>>(src, dst, a1);
    edge_pass_b<<<edge_blocks, 256>>>(src, dst);

    // ---- Layer 2 (K = HD = 192, X = g_out)
    sgemm_fused_kernel<<<gemm_grid, 256>>>(nullptr, W2s, W2d, HD, 1);
    init_layer_kernel<<<init_blocks, 256>>>(b2);
    edge_pass_a<<<edge_blocks, 256>>>(src, dst, a2);
    edge_pass_b<<<edge_blocks, 256>>>(src, dst);

    // ---- Layer 3
    sgemm_fused_kernel<<<gemm_grid, 256>>>(nullptr, W3s, W3d, HD, 1);
    init_layer_kernel<<<init_blocks, 256>>>(b3);
    edge_pass_a<<<edge_blocks, 256>>>(src, dst, a3);
    edge_pass_b<<<edge_blocks, 256>>>(src, dst);

    // ---- pooling + head
    pool_zero_kernel<<<17, 256>>>();
    pool_kernel<<<pool_blocks, 256>>>(gid);
    head_kernel<<<1, 256>>>(p1, p2, p3, Wex, bex, Wpat, bpat,
                            Wc1, bc1, Wc2, bc2, Wc3, bc3, (float*)d_out);
}

// round 4
// speedup vs baseline: 1.5226x; 1.1628x over previous
#include <cuda_runtime.h>
#include <math.h>
#include <stdint.h>

#define NN   50000
#define EE   400000
#define F_IN 128
#define HH   3
#define DD   64
#define HD   192
#define GG   64
#define PP   64
#define NEG_GAT 0.2f
#define NEG  0.01f

// ---------------- device scratch ----------------
__device__ __align__(16) float g_fs[(size_t)NN * HD];
__device__ __align__(16) float g_fd[(size_t)NN * HD];
__device__ __align__(16) float g_out[(size_t)NN * HD];
__device__ int g_deg[NN];
__device__ int g_rowptr[NN + 1];
__device__ int g_cur[NN];
__device__ int g_esrc[EE];
__device__ float g_pool[GG * DD];
__device__ float g_cnt[GG];

// ---------------- CSR build (graph static across layers) ----------------
__global__ void zero_deg_kernel() {
    int i = blockIdx.x * blockDim.x + threadIdx.x;
    if (i < NN) g_deg[i] = 0;
}
__global__ void hist_kernel(const int* __restrict__ dst) {
    int e = blockIdx.x * blockDim.x + threadIdx.x;
    if (e < EE) atomicAdd(&g_deg[dst[e]], 1);
}
__global__ void scan_kernel() {
    __shared__ int sp[1024];
    int tid = threadIdx.x;
    int start = tid * 49;
    int end = start + 49; if (end > NN) end = NN;
    int loc = 0;
    for (int i = start; i < end; i++) loc += g_deg[i];
    sp[tid] = loc;
    __syncthreads();
    for (int off = 1; off < 1024; off <<= 1) {
        int v = (tid >= off) ? sp[tid - off] : 0;
        __syncthreads();
        sp[tid] += v;
        __syncthreads();
    }
    int run = sp[tid] - loc;
    for (int i = start; i < end; i++) {
        g_rowptr[i] = run; g_cur[i] = run; run += g_deg[i];
    }
    if (tid == 1023) g_rowptr[NN] = run;
}
__global__ void scatter_kernel(const int* __restrict__ src, const int* __restrict__ dst) {
    int e = blockIdx.x * blockDim.x + threadIdx.x;
    if (e >= EE) return;
    int pos = atomicAdd(&g_cur[dst[e]], 1);
    g_esrc[pos] = src[e];
}

// ---------------- Fused SGEMM: [g_fs | g_fd] = A[M,K] @ [Ws | Wd]  (N = 384) ----
#define BM 128
#define BN 128
#define BK 16

__global__ __launch_bounds__(256) void sgemm_fused_kernel(
        const float* __restrict__ Xext,
        const float* __restrict__ Ws,
        const float* __restrict__ Wd,
        int K, int use_internal_x) {
    const float* __restrict__ A = use_internal_x ? g_out : Xext;

    __shared__ float As[BK][BM];
    __shared__ float Bs[BK][BN];

    const int tid  = threadIdx.x;
    const int row0 = blockIdx.x * BM;
    const int col0 = blockIdx.y * BN;

    const int ty4 = (tid >> 4) << 2;
    const int tx4 = (tid & 15) << 2;

    const int arow  = tid >> 1;
    const int acol8 = (tid & 1) << 3;
    const int brow  = tid >> 4;
    const int bcol4 = (tid & 15) << 2;

    float acc[8][8];
#pragma unroll
    for (int i = 0; i < 8; i++)
#pragma unroll
        for (int j = 0; j < 8; j++) acc[i][j] = 0.f;

    const int nk = K / BK;

    float4 pa0, pa1, pb0, pb1;
    {
        int gr = row0 + arow;
        pa0 = make_float4(0.f, 0.f, 0.f, 0.f);
        pa1 = pa0;
        if (gr < NN) {
            pa0 = *reinterpret_cast<const float4*>(A + (size_t)gr * K + acol8);
            pa1 = *reinterpret_cast<const float4*>(A + (size_t)gr * K + acol8 + 4);
        }
        int cg0 = col0 + bcol4;
        int cg1 = cg0 + 64;
        pb0 = (cg0 < HD)
            ? *reinterpret_cast<const float4*>(Ws + (size_t)brow * HD + cg0)
            : *reinterpret_cast<const float4*>(Wd + (size_t)brow * HD + (cg0 - HD));
        pb1 = (cg1 < HD)
            ? *reinterpret_cast<const float4*>(Ws + (size_t)brow * HD + cg1)
            : *reinterpret_cast<const float4*>(Wd + (size_t)brow * HD + (cg1 - HD));
    }

    for (int t = 0; t < nk; t++) {
        __syncthreads();
        As[acol8 + 0][arow] = pa0.x;
        As[acol8 + 1][arow] = pa0.y;
        As[acol8 + 2][arow] = pa0.z;
        As[acol8 + 3][arow] = pa0.w;
        As[acol8 + 4][arow] = pa1.x;
        As[acol8 + 5][arow] = pa1.y;
        As[acol8 + 6][arow] = pa1.z;
        As[acol8 + 7][arow] = pa1.w;
        *reinterpret_cast<float4*>(&Bs[brow][bcol4])      = pb0;
        *reinterpret_cast<float4*>(&Bs[brow][bcol4 + 64]) = pb1;
        __syncthreads();

        if (t + 1 < nk) {
            int k0 = (t + 1) * BK;
            int gr = row0 + arow;
            pa0 = make_float4(0.f, 0.f, 0.f, 0.f);
            pa1 = pa0;
            if (gr < NN) {
                pa0 = *reinterpret_cast<const float4*>(A + (size_t)gr * K + k0 + acol8);
                pa1 = *reinterpret_cast<const float4*>(A + (size_t)gr * K + k0 + acol8 + 4);
            }
            int cg0 = col0 + bcol4;
            int cg1 = cg0 + 64;
            pb0 = (cg0 < HD)
                ? *reinterpret_cast<const float4*>(Ws + (size_t)(k0 + brow) * HD + cg0)
                : *reinterpret_cast<const float4*>(Wd + (size_t)(k0 + brow) * HD + (cg0 - HD));
            pb1 = (cg1 < HD)
                ? *reinterpret_cast<const float4*>(Ws + (size_t)(k0 + brow) * HD + cg1)
                : *reinterpret_cast<const float4*>(Wd + (size_t)(k0 + brow) * HD + (cg1 - HD));
        }

#pragma unroll
        for (int k = 0; k < BK; k++) {
            float4 a0 = *reinterpret_cast<const float4*>(&As[k][ty4]);
            float4 a1 = *reinterpret_cast<const float4*>(&As[k][ty4 + 64]);
            float4 b0 = *reinterpret_cast<const float4*>(&Bs[k][tx4]);
            float4 b1 = *reinterpret_cast<const float4*>(&Bs[k][tx4 + 64]);
            float ar[8] = {a0.x, a0.y, a0.z, a0.w, a1.x, a1.y, a1.z, a1.w};
            float br[8] = {b0.x, b0.y, b0.z, b0.w, b1.x, b1.y, b1.z, b1.w};
#pragma unroll
            for (int i = 0; i < 8; i++)
#pragma unroll
                for (int j = 0; j < 8; j++) acc[i][j] += ar[i] * br[j];
        }
    }

#pragma unroll
    for (int i = 0; i < 8; i++) {
        int row = row0 + ty4 + (i & 3) + ((i >> 2) << 6);
        if (row >= NN) continue;
        int cg0 = col0 + tx4;
        int cg1 = cg0 + 64;
        float4 v0 = make_float4(acc[i][0], acc[i][1], acc[i][2], acc[i][3]);
        float4 v1 = make_float4(acc[i][4], acc[i][5], acc[i][6], acc[i][7]);
        if (cg0 < HD)
            *reinterpret_cast<float4*>(g_fs + (size_t)row * HD + cg0) = v0;
        else
            *reinterpret_cast<float4*>(g_fd + (size_t)row * HD + (cg0 - HD)) = v0;
        if (cg1 < HD)
            *reinterpret_cast<float4*>(g_fs + (size_t)row * HD + cg1) = v1;
        else
            *reinterpret_cast<float4*>(g_fd + (size_t)row * HD + (cg1 - HD)) = v1;
    }
}

// ---------------- fused single-pass GATv2 message passing: one warp per node ------
// out[n] = (Σ_e ex_e * fs[src_e]) / (Σ_e ex_e) + bias     (softmax normalization
// folded into a single edge sweep; max-subtraction is a no-op for alpha)
// do_pool: skip g_out write; emit head-mean directly into per-graph pool atomics.
__global__ void gat_node_kernel(const float* __restrict__ attn,
                                const float* __restrict__ bias,
                                int do_pool, const int* __restrict__ gid) {
    int gw = (blockIdx.x * blockDim.x + threadIdx.x) >> 5;
    if (gw >= NN) return;
    int lane = threadIdx.x & 31;
    int n = gw;
    int p0 = g_rowptr[n], p1 = g_rowptr[n + 1];

    const float2* a2  = reinterpret_cast<const float2*>(attn);
    const float2* fd2 = reinterpret_cast<const float2*>(g_fd + (size_t)n * HD);
    float2 va0 = a2[lane], va1 = a2[lane + 32], va2 = a2[lane + 64];
    float2 vd0 = fd2[lane], vd1 = fd2[lane + 32], vd2 = fd2[lane + 64];

    float den0 = 0.f, den1 = 0.f, den2 = 0.f;
    float2 acc0 = make_float2(0.f, 0.f), acc1 = acc0, acc2 = acc0;

    for (int p = p0; p < p1; p++) {
        int s = g_esrc[p];
        const float2* fs2 = reinterpret_cast<const float2*>(g_fs + (size_t)s * HD);
        float2 u0 = fs2[lane], u1 = fs2[lane + 32], u2 = fs2[lane + 64];
        float x, y, l0, l1, l2;
        x = u0.x + vd0.x; x = x > 0.f ? x : NEG_GAT * x;
        y = u0.y + vd0.y; y = y > 0.f ? y : NEG_GAT * y;
        l0 = x * va0.x + y * va0.y;
        x = u1.x + vd1.x; x = x > 0.f ? x : NEG_GAT * x;
        y = u1.y + vd1.y; y = y > 0.f ? y : NEG_GAT * y;
        l1 = x * va1.x + y * va1.y;
        x = u2.x + vd2.x; x = x > 0.f ? x : NEG_GAT * x;
        y = u2.y + vd2.y; y = y > 0.f ? y : NEG_GAT * y;
        l2 = x * va2.x + y * va2.y;
#pragma unroll
        for (int o = 16; o; o >>= 1) {
            l0 += __shfl_xor_sync(0xffffffffu, l0, o);
            l1 += __shfl_xor_sync(0xffffffffu, l1, o);
            l2 += __shfl_xor_sync(0xffffffffu, l2, o);
        }
        float e0 = expf(l0), e1 = expf(l1), e2 = expf(l2);
        den0 += e0; den1 += e1; den2 += e2;
        acc0.x += e0 * u0.x; acc0.y += e0 * u0.y;
        acc1.x += e1 * u1.x; acc1.y += e1 * u1.y;
        acc2.x += e2 * u2.x; acc2.y += e2 * u2.y;
    }

    float i0 = 1.f / fmaxf(den0, 1e-9f);
    float i1 = 1.f / fmaxf(den1, 1e-9f);
    float i2 = 1.f / fmaxf(den2, 1e-9f);

    const float2* b2 = reinterpret_cast<const float2*>(bias);
    float2 w0 = b2[lane], w1 = b2[lane + 32], w2 = b2[lane + 64];
    float2 o0 = make_float2(acc0.x * i0 + w0.x, acc0.y * i0 + w0.y);
    float2 o1 = make_float2(acc1.x * i1 + w1.x, acc1.y * i1 + w1.y);
    float2 o2 = make_float2(acc2.x * i2 + w2.x, acc2.y * i2 + w2.y);

    if (!do_pool) {
        float2* op = reinterpret_cast<float2*>(g_out + (size_t)n * HD);
        op[lane] = o0; op[lane + 32] = o1; op[lane + 64] = o2;
    } else {
        int g = gid[n];
        float vx = (o0.x + o1.x + o2.x) * (1.f / 3.f);
        float vy = (o0.y + o1.y + o2.y) * (1.f / 3.f);
        atomicAdd(&g_pool[g * DD + 2 * lane], vx);
        atomicAdd(&g_pool[g * DD + 2 * lane + 1], vy);
        if (lane == 0) atomicAdd(&g_cnt[g], 1.f);
    }
}

// ---------------- pool zero ----------------
__global__ void pool_zero_kernel() {
    int i = blockIdx.x * blockDim.x + threadIdx.x;
    if (i < GG * DD) g_pool[i] = 0.f;
    if (i < GG) g_cnt[i] = 0.f;
}

// ---------------- pattern branch + classifier head ----------------
__global__ void head_kernel(const float* __restrict__ p1, const float* __restrict__ p2,
                            const float* __restrict__ p3,
                            const float* __restrict__ Wex, const float* __restrict__ bex,
                            const float* __restrict__ Wpat, const float* __restrict__ bpat,
                            const float* __restrict__ Wc1, const float* __restrict__ bc1,
                            const float* __restrict__ Wc2, const float* __restrict__ bc2,
                            const float* __restrict__ Wc3, const float* __restrict__ bc3,
                            float* __restrict__ outp) {
    __shared__ float s_px[GG * 96];
    __shared__ float s_pat[GG * 64];
    int tid = threadIdx.x;

    for (int idx = tid; idx < GG * 96; idx += 256) {
        int g = idx / 96, j = idx % 96;
        const float* p = (j < 32) ? p1 : (j < 64 ? p2 : p3);
        int jj = j & 31;
        float s = bex[jj];
        for (int k = 0; k < PP; k++) s += p[g * PP + k] * Wex[k * 32 + jj];
        s_px[idx] = s;
    }
    __syncthreads();
    for (int idx = tid; idx < GG * 64; idx += 256) {
        int g = idx >> 6, j = idx & 63;
        float s = bpat[j];
        for (int k = 0; k < 96; k++) s += s_px[g * 96 + k] * Wpat[k * 64 + j];
        s_pat[idx] = s > 0.f ? s : NEG * s;
    }
    __syncthreads();
    for (int idx = tid; idx < GG * 64; idx += 256) {
        int g = idx >> 6, j = idx & 63;
        float s = bc1[j];
        float inv = 1.f / fmaxf(g_cnt[g], 1.f);
        for (int k = 0; k < 64; k++) s += (g_pool[g * 64 + k] * inv) * Wc1[k * 64 + j];
        for (int k = 0; k < 64; k++) s += s_pat[g * 64 + k] * Wc1[(64 + k) * 64 + j];
        s_px[idx] = s > 0.f ? s : NEG * s;
    }
    __syncthreads();
    for (int idx = tid; idx < GG * 32; idx += 256) {
        int g = idx >> 5, j = idx & 31;
        float s = bc2[j];
        for (int k = 0; k < 64; k++) s += s_px[g * 64 + k] * Wc2[k * 32 + j];
        s_px[4096 + idx] = s > 0.f ? s : NEG * s;
    }
    __syncthreads();
    for (int idx = tid; idx < GG * 2; idx += 256) {
        int g = idx >> 1, j = idx & 1;
        float s = bc3[j];
        for (int k = 0; k < 32; k++) s += s_px[4096 + g * 32 + k] * Wc3[k * 2 + j];
        outp[idx] = s;
    }
}

// ---------------- launcher ----------------
extern "C" void kernel_launch(void* const* d_in, const int* in_sizes, int n_in,
                              void* d_out, int out_size) {
    const float* x_in = (const float*)d_in[0];
    const int*   src  = (const int*)d_in[1];
    const int*   dst  = (const int*)d_in[2];
    const int*   gid  = (const int*)d_in[3];
    const float* p1   = (const float*)d_in[4];
    const float* p2   = (const float*)d_in[5];
    const float* p3   = (const float*)d_in[6];
    const float* W1s = (const float*)d_in[7],  *W1d = (const float*)d_in[8];
    const float* a1  = (const float*)d_in[9],  *b1  = (const float*)d_in[10];
    const float* W2s = (const float*)d_in[11], *W2d = (const float*)d_in[12];
    const float* a2  = (const float*)d_in[13], *b2  = (const float*)d_in[14];
    const float* W3s = (const float*)d_in[15], *W3d = (const float*)d_in[16];
    const float* a3  = (const float*)d_in[17], *b3  = (const float*)d_in[18];
    const float* Wex = (const float*)d_in[19], *bex = (const float*)d_in[20];
    const float* Wpat= (const float*)d_in[21], *bpat= (const float*)d_in[22];
    const float* Wc1 = (const float*)d_in[23], *bc1 = (const float*)d_in[24];
    const float* Wc2 = (const float*)d_in[25], *bc2 = (const float*)d_in[26];
    const float* Wc3 = (const float*)d_in[27], *bc3 = (const float*)d_in[28];

    dim3 gemm_grid((NN + BM - 1) / BM, (2 * HD) / BN);   // (391, 3)
    int  node_blocks = (NN * 32 + 255) / 256;            // 6250

    // CSR build (graph static across layers) + pool zero (independent)
    zero_deg_kernel<<<(NN + 255) / 256, 256>>>();
    hist_kernel<<<(EE + 255) / 256, 256>>>(dst);
    scan_kernel<<<1, 1024>>>();
    scatter_kernel<<<(EE + 255) / 256, 256>>>(src, dst);
    pool_zero_kernel<<<17, 256>>>();

    // ---- Layer 1 (K = F_IN = 128)
    sgemm_fused_kernel<<<gemm_grid, 256>>>(x_in, W1s, W1d, F_IN, 0);
    gat_node_kernel<<<node_blocks, 256>>>(a1, b1, 0, gid);

    // ---- Layer 2 (K = HD = 192)
    sgemm_fused_kernel<<<gemm_grid, 256>>>(nullptr, W2s, W2d, HD, 1);
    gat_node_kernel<<<node_blocks, 256>>>(a2, b2, 0, gid);

    // ---- Layer 3 (pooling fused; g_out never written)
    sgemm_fused_kernel<<<gemm_grid, 256>>>(nullptr, W3s, W3d, HD, 1);
    gat_node_kernel<<<node_blocks, 256>>>(a3, b3, 1, gid);

    // ---- head
    head_kernel<<<1, 256>>>(p1, p2, p3, Wex, bex, Wpat, bpat,
                            Wc1, bc1, Wc2, bc2, Wc3, bc3, (float*)d_out);
}

// round 5
// speedup vs baseline: 2.3612x; 1.5508x over previous
#include <cuda_runtime.h>
#include <cuda_bf16.h>
#include <math.h>
#include <stdint.h>

#define NN   50000
#define EE   400000
#define F_IN 128
#define HH   3
#define DD   64
#define HD   192
#define GG   64
#define PP   64
#define NEG_GAT 0.2f
#define NEG  0.01f

// ---------------- device scratch ----------------
__device__ __align__(16) float g_fs[(size_t)NN * HD];
__device__ __align__(16) float g_fd[(size_t)NN * HD];
__device__ __align__(16) __nv_bfloat16 g_xh[(size_t)NN * HD];   // activation hi (bf16 split)
__device__ __align__(16) __nv_bfloat16 g_xl[(size_t)NN * HD];   // activation lo
__device__ __align__(16) __nv_bfloat16 g_wh[(size_t)HD * 384];  // [K][384] weight hi
__device__ __align__(16) __nv_bfloat16 g_wl[(size_t)HD * 384];  // weight lo
__device__ int g_deg[NN];
__device__ int g_rowptr[NN + 1];
__device__ int g_cur[NN];
__device__ int g_esrc[EE];
__device__ float g_pool[GG * DD];
__device__ float g_cnt[GG];

// ---------------- PTX helpers ----------------
__device__ __forceinline__ uint32_t cvta_shared_u32(const void* p) {
    uint32_t a;
    asm("{ .reg .u64 t; cvta.to.shared.u64 t, %1; cvt.u32.u64 %0, t; }" : "=r"(a) : "l"(p));
    return a;
}
__device__ __forceinline__ void cpasync16(uint32_t smem, const void* g, int srcsize) {
    asm volatile("cp.async.cg.shared.global [%0], [%1], 16, %2;"
                 :: "r"(smem), "l"(g), "r"(srcsize) : "memory");
}
__device__ __forceinline__ void cp_commit() {
    asm volatile("cp.async.commit_group;" ::: "memory");
}
template <int N> __device__ __forceinline__ void cp_wait() {
    asm volatile("cp.async.wait_group %0;" :: "n"(N) : "memory");
}
__device__ __forceinline__ void ldsm4(uint32_t* r, uint32_t addr) {
    asm volatile("ldmatrix.sync.aligned.m8n8.x4.shared.b16 {%0,%1,%2,%3}, [%4];"
                 : "=r"(r[0]), "=r"(r[1]), "=r"(r[2]), "=r"(r[3]) : "r"(addr));
}
__device__ __forceinline__ void ldsm4t(uint32_t* r, uint32_t addr) {
    asm volatile("ldmatrix.sync.aligned.m8n8.x4.trans.shared.b16 {%0,%1,%2,%3}, [%4];"
                 : "=r"(r[0]), "=r"(r[1]), "=r"(r[2]), "=r"(r[3]) : "r"(addr));
}
__device__ __forceinline__ void mma16816(float* c, const uint32_t* a, const uint32_t* b) {
    asm volatile("mma.sync.aligned.m16n8k16.row.col.f32.bf16.bf16.f32 "
                 "{%0,%1,%2,%3}, {%4,%5,%6,%7}, {%8,%9}, {%0,%1,%2,%3};"
                 : "+f"(c[0]), "+f"(c[1]), "+f"(c[2]), "+f"(c[3])
                 : "r"(a[0]), "r"(a[1]), "r"(a[2]), "r"(a[3]), "r"(b[0]), "r"(b[1]));
}
__device__ __forceinline__ void store_split(float2 v, __nv_bfloat162* h, __nv_bfloat162* l) {
    __nv_bfloat16 hx = __float2bfloat16(v.x);
    __nv_bfloat16 hy = __float2bfloat16(v.y);
    __nv_bfloat162 hv; hv.x = hx; hv.y = hy;
    __nv_bfloat162 lv;
    lv.x = __float2bfloat16(v.x - __bfloat162float(hx));
    lv.y = __float2bfloat16(v.y - __bfloat162float(hy));
    *h = hv; *l = lv;
}

// ---------------- CSR build (graph static across layers) ----------------
__global__ void zero_deg_kernel() {
    int i = blockIdx.x * blockDim.x + threadIdx.x;
    if (i < NN) g_deg[i] = 0;
}
__global__ void hist_kernel(const int* __restrict__ dst) {
    int e = blockIdx.x * blockDim.x + threadIdx.x;
    if (e < EE) atomicAdd(&g_deg[dst[e]], 1);
}
__global__ void scan_kernel() {
    __shared__ int sp[1024];
    int tid = threadIdx.x;
    int start = tid * 49;
    int end = start + 49; if (end > NN) end = NN;
    int loc = 0;
    for (int i = start; i < end; i++) loc += g_deg[i];
    sp[tid] = loc;
    __syncthreads();
    for (int off = 1; off < 1024; off <<= 1) {
        int v = (tid >= off) ? sp[tid - off] : 0;
        __syncthreads();
        sp[tid] += v;
        __syncthreads();
    }
    int run = sp[tid] - loc;
    for (int i = start; i < end; i++) {
        g_rowptr[i] = run; g_cur[i] = run; run += g_deg[i];
    }
    if (tid == 1023) g_rowptr[NN] = run;
}
__global__ void scatter_kernel(const int* __restrict__ src, const int* __restrict__ dst) {
    int e = blockIdx.x * blockDim.x + threadIdx.x;
    if (e >= EE) return;
    int pos = atomicAdd(&g_cur[dst[e]], 1);
    g_esrc[pos] = src[e];
}

// ---------------- operand conversions ----------------
__global__ void convert_x_kernel(const float* __restrict__ x) {
    int idx = blockIdx.x * blockDim.x + threadIdx.x;
    if (idx >= NN * F_IN / 4) return;
    float4 v = reinterpret_cast<const float4*>(x)[idx];
    __nv_bfloat162 h0, l0, h1, l1;
    store_split(make_float2(v.x, v.y), &h0, &l0);
    store_split(make_float2(v.z, v.w), &h1, &l1);
    __nv_bfloat162* oh = reinterpret_cast<__nv_bfloat162*>(g_xh);
    __nv_bfloat162* ol = reinterpret_cast<__nv_bfloat162*>(g_xl);
    oh[idx * 2] = h0; oh[idx * 2 + 1] = h1;
    ol[idx * 2] = l0; ol[idx * 2 + 1] = l1;
}
__global__ void convert_w_kernel(const float* __restrict__ Ws, const float* __restrict__ Wd, int K) {
    int idx = blockIdx.x * blockDim.x + threadIdx.x;
    if (idx >= K * 384) return;
    int k = idx / 384, n = idx % 384;
    float w = (n < HD) ? Ws[(size_t)k * HD + n] : Wd[(size_t)k * HD + n - HD];
    __nv_bfloat16 h = __float2bfloat16(w);
    g_wh[idx] = h;
    g_wl[idx] = __float2bfloat16(w - __bfloat162float(h));
}

// ---------------- mma.sync split-bf16 GEMM: [g_fs|g_fd] = X @ [Ws|Wd] ------------
// BM=128, BN=128, BK=32, 8 warps (2x4), warp tile 64x32, 3-term split
// smem strides: A 40 halves (80B, conflict-free ldsm), B 136 halves (272B)
#define STAGE_BYTES 37888
#define SA_LO 10240
#define SB_HI 20480
#define GEMM_SMEM (2 * STAGE_BYTES)

__global__ __launch_bounds__(256) void gemm_mma_kernel(int K) {
    extern __shared__ char smdyn[];
    uint32_t smb = cvta_shared_u32(smdyn);
    int tid = threadIdx.x, lane = tid & 31;
    int wid = tid >> 5, wr = wid & 1, wc = wid >> 1;
    int row0 = blockIdx.x * 128, col0 = blockIdx.y * 128;
    int nk = K >> 5;

    float c[4][4][4];
#pragma unroll
    for (int i = 0; i < 4; i++)
#pragma unroll
        for (int j = 0; j < 4; j++)
#pragma unroll
            for (int k = 0; k < 4; k++) c[i][j][k] = 0.f;

    auto issue = [&](int t, int st) {
        int k0 = t << 5;
        uint32_t sb = smb + st * STAGE_BYTES;
#pragma unroll
        for (int h = 0; h < 2; h++) {
            int cc = tid + h * 256;
            // A chunk: 512 chunks, row = cc>>2 (0..127), cg = (cc&3)*8
            int ar = cc >> 2, acg = (cc & 3) << 3;
            int grow = row0 + ar;
            int ok = (grow < NN) ? 16 : 0;
            const __nv_bfloat16* ph = ok ? (g_xh + (size_t)grow * K + k0 + acg) : g_xh;
            const __nv_bfloat16* pl = ok ? (g_xl + (size_t)grow * K + k0 + acg) : g_xl;
            uint32_t da = sb + ar * 80 + (acg << 1);
            cpasync16(da, ph, ok);
            cpasync16(da + SA_LO, pl, ok);
            // B chunk: 512 chunks, row = cc>>4 (0..31), cg = (cc&15)*8
            int br = cc >> 4, bcg = (cc & 15) << 3;
            const __nv_bfloat16* qh = g_wh + (size_t)(k0 + br) * 384 + col0 + bcg;
            const __nv_bfloat16* ql = g_wl + (size_t)(k0 + br) * 384 + col0 + bcg;
            uint32_t db = sb + SB_HI + br * 272 + (bcg << 1);
            cpasync16(db, qh, 16);
            cpasync16(db + 8704, ql, 16);
        }
        cp_commit();
    };

    issue(0, 0);

    const int arow = wr * 64 + (lane & 15);
    const int acol = (lane >> 4) << 3;       // 0 or 8 halves
    const int krow = (lane & 15);
    const int ncll = wc * 32 + ((lane >> 4) << 3);

    for (int t = 0; t < nk; t++) {
        int st = t & 1;
        if (t + 1 < nk) { issue(t + 1, st ^ 1); cp_wait<1>(); }
        else            { cp_wait<0>(); }
        __syncthreads();
        uint32_t sb = smb + st * STAGE_BYTES;
#pragma unroll
        for (int ks = 0; ks < 2; ks++) {
            uint32_t Ah[4][4], Al[4][4], B[4][2];
#pragma unroll
            for (int mt = 0; mt < 4; mt++) {
                uint32_t ad = sb + (arow + mt * 16) * 80 + ((ks * 16 + acol) << 1);
                ldsm4(Ah[mt], ad);
                ldsm4(Al[mt], ad + SA_LO);
            }
            uint32_t bk = sb + SB_HI + (ks * 16 + krow) * 272;
#pragma unroll
            for (int np = 0; np < 2; np++) {
                uint32_t r[4];
                ldsm4t(r, bk + ((ncll + np * 16) << 1));
                B[2*np][0] = r[0]; B[2*np][1] = r[1];
                B[2*np+1][0] = r[2]; B[2*np+1][1] = r[3];
            }
#pragma unroll
            for (int mt = 0; mt < 4; mt++)
#pragma unroll
                for (int nt = 0; nt < 4; nt++) mma16816(c[mt][nt], Ah[mt], B[nt]);
#pragma unroll
            for (int mt = 0; mt < 4; mt++)
#pragma unroll
                for (int nt = 0; nt < 4; nt++) mma16816(c[mt][nt], Al[mt], B[nt]);
            // B lo
#pragma unroll
            for (int np = 0; np < 2; np++) {
                uint32_t r[4];
                ldsm4t(r, bk + 8704 + ((ncll + np * 16) << 1));
                B[2*np][0] = r[0]; B[2*np][1] = r[1];
                B[2*np+1][0] = r[2]; B[2*np+1][1] = r[3];
            }
#pragma unroll
            for (int mt = 0; mt < 4; mt++)
#pragma unroll
                for (int nt = 0; nt < 4; nt++) mma16816(c[mt][nt], Ah[mt], B[nt]);
        }
        __syncthreads();
    }

    // epilogue: c0,c1 -> (row, col..col+1); c2,c3 -> (row+8, ...)
    int gid4 = lane >> 2, tig = lane & 3;
#pragma unroll
    for (int mt = 0; mt < 4; mt++) {
        int rg = row0 + wr * 64 + mt * 16 + gid4;
#pragma unroll
        for (int nt = 0; nt < 4; nt++) {
            int col = col0 + wc * 32 + nt * 8 + tig * 2;
            float* base = (col < HD) ? (g_fs + col) : (g_fd + (col - HD));
            if (rg < NN)
                *reinterpret_cast<float2*>(base + (size_t)rg * HD) =
                    make_float2(c[mt][nt][0], c[mt][nt][1]);
            if (rg + 8 < NN)
                *reinterpret_cast<float2*>(base + (size_t)(rg + 8) * HD) =
                    make_float2(c[mt][nt][2], c[mt][nt][3]);
        }
    }
}

// ---------------- fused single-pass GATv2: one warp per node ----------------------
// out = (Σ ex·fs[src])/(Σ ex) + bias; layers 1-2 emit split-bf16 activations for
// the next GEMM; layer 3 pools head-mean directly into per-graph atomics.
__global__ void gat_node_kernel(const float* __restrict__ attn,
                                const float* __restrict__ bias,
                                int do_pool, const int* __restrict__ gid) {
    int gw = (blockIdx.x * blockDim.x + threadIdx.x) >> 5;
    if (gw >= NN) return;
    int lane = threadIdx.x & 31;
    int n = gw;
    int p0 = g_rowptr[n], p1 = g_rowptr[n + 1];

    const float2* a2  = reinterpret_cast<const float2*>(attn);
    const float2* fd2 = reinterpret_cast<const float2*>(g_fd + (size_t)n * HD);
    float2 va0 = a2[lane], va1 = a2[lane + 32], va2 = a2[lane + 64];
    float2 vd0 = fd2[lane], vd1 = fd2[lane + 32], vd2 = fd2[lane + 64];

    float den0 = 0.f, den1 = 0.f, den2 = 0.f;
    float2 acc0 = make_float2(0.f, 0.f), acc1 = acc0, acc2 = acc0;

    for (int p = p0; p < p1; p++) {
        int s = g_esrc[p];
        const float2* fs2 = reinterpret_cast<const float2*>(g_fs + (size_t)s * HD);
        float2 u0 = fs2[lane], u1 = fs2[lane + 32], u2 = fs2[lane + 64];
        float x, y, l0, l1, l2;
        x = u0.x + vd0.x; x = x > 0.f ? x : NEG_GAT * x;
        y = u0.y + vd0.y; y = y > 0.f ? y : NEG_GAT * y;
        l0 = x * va0.x + y * va0.y;
        x = u1.x + vd1.x; x = x > 0.f ? x : NEG_GAT * x;
        y = u1.y + vd1.y; y = y > 0.f ? y : NEG_GAT * y;
        l1 = x * va1.x + y * va1.y;
        x = u2.x + vd2.x; x = x > 0.f ? x : NEG_GAT * x;
        y = u2.y + vd2.y; y = y > 0.f ? y : NEG_GAT * y;
        l2 = x * va2.x + y * va2.y;
#pragma unroll
        for (int o = 16; o; o >>= 1) {
            l0 += __shfl_xor_sync(0xffffffffu, l0, o);
            l1 += __shfl_xor_sync(0xffffffffu, l1, o);
            l2 += __shfl_xor_sync(0xffffffffu, l2, o);
        }
        float e0 = expf(l0), e1 = expf(l1), e2 = expf(l2);
        den0 += e0; den1 += e1; den2 += e2;
        acc0.x += e0 * u0.x; acc0.y += e0 * u0.y;
        acc1.x += e1 * u1.x; acc1.y += e1 * u1.y;
        acc2.x += e2 * u2.x; acc2.y += e2 * u2.y;
    }

    float i0 = 1.f / fmaxf(den0, 1e-9f);
    float i1 = 1.f / fmaxf(den1, 1e-9f);
    float i2 = 1.f / fmaxf(den2, 1e-9f);

    const float2* b2 = reinterpret_cast<const float2*>(bias);
    float2 w0 = b2[lane], w1 = b2[lane + 32], w2 = b2[lane + 64];
    float2 o0 = make_float2(acc0.x * i0 + w0.x, acc0.y * i0 + w0.y);
    float2 o1 = make_float2(acc1.x * i1 + w1.x, acc1.y * i1 + w1.y);
    float2 o2 = make_float2(acc2.x * i2 + w2.x, acc2.y * i2 + w2.y);

    if (!do_pool) {
        __nv_bfloat162* oh = reinterpret_cast<__nv_bfloat162*>(g_xh + (size_t)n * HD);
        __nv_bfloat162* ol = reinterpret_cast<__nv_bfloat162*>(g_xl + (size_t)n * HD);
        store_split(o0, &oh[lane],      &ol[lane]);
        store_split(o1, &oh[lane + 32], &ol[lane + 32]);
        store_split(o2, &oh[lane + 64], &ol[lane + 64]);
    } else {
        int g = gid[n];
        float vx = (o0.x + o1.x + o2.x) * (1.f / 3.f);
        float vy = (o0.y + o1.y + o2.y) * (1.f / 3.f);
        atomicAdd(&g_pool[g * DD + 2 * lane], vx);
        atomicAdd(&g_pool[g * DD + 2 * lane + 1], vy);
        if (lane == 0) atomicAdd(&g_cnt[g], 1.f);
    }
}

// ---------------- pool zero ----------------
__global__ void pool_zero_kernel() {
    int i = blockIdx.x * blockDim.x + threadIdx.x;
    if (i < GG * DD) g_pool[i] = 0.f;
    if (i < GG) g_cnt[i] = 0.f;
}

// ---------------- pattern branch + classifier head ----------------
__global__ void head_kernel(const float* __restrict__ p1, const float* __restrict__ p2,
                            const float* __restrict__ p3,
                            const float* __restrict__ Wex, const float* __restrict__ bex,
                            const float* __restrict__ Wpat, const float* __restrict__ bpat,
                            const float* __restrict__ Wc1, const float* __restrict__ bc1,
                            const float* __restrict__ Wc2, const float* __restrict__ bc2,
                            const float* __restrict__ Wc3, const float* __restrict__ bc3,
                            float* __restrict__ outp) {
    __shared__ float s_px[GG * 96];
    __shared__ float s_pat[GG * 64];
    int tid = threadIdx.x;

    for (int idx = tid; idx < GG * 96; idx += 256) {
        int g = idx / 96, j = idx % 96;
        const float* p = (j < 32) ? p1 : (j < 64 ? p2 : p3);
        int jj = j & 31;
        float s = bex[jj];
        for (int k = 0; k < PP; k++) s += p[g * PP + k] * Wex[k * 32 + jj];
        s_px[idx] = s;
    }
    __syncthreads();
    for (int idx = tid; idx < GG * 64; idx += 256) {
        int g = idx >> 6, j = idx & 63;
        float s = bpat[j];
        for (int k = 0; k < 96; k++) s += s_px[g * 96 + k] * Wpat[k * 64 + j];
        s_pat[idx] = s > 0.f ? s : NEG * s;
    }
    __syncthreads();
    for (int idx = tid; idx < GG * 64; idx += 256) {
        int g = idx >> 6, j = idx & 63;
        float s = bc1[j];
        float inv = 1.f / fmaxf(g_cnt[g], 1.f);
        for (int k = 0; k < 64; k++) s += (g_pool[g * 64 + k] * inv) * Wc1[k * 64 + j];
        for (int k = 0; k < 64; k++) s += s_pat[g * 64 + k] * Wc1[(64 + k) * 64 + j];
        s_px[idx] = s > 0.f ? s : NEG * s;
    }
    __syncthreads();
    for (int idx = tid; idx < GG * 32; idx += 256) {
        int g = idx >> 5, j = idx & 31;
        float s = bc2[j];
        for (int k = 0; k < 64; k++) s += s_px[g * 64 + k] * Wc2[k * 32 + j];
        s_px[4096 + idx] = s > 0.f ? s : NEG * s;
    }
    __syncthreads();
    for (int idx = tid; idx < GG * 2; idx += 256) {
        int g = idx >> 1, j = idx & 1;
        float s = bc3[j];
        for (int k = 0; k < 32; k++) s += s_px[4096 + g * 32 + k] * Wc3[k * 2 + j];
        outp[idx] = s;
    }
}

// ---------------- launcher ----------------
extern "C" void kernel_launch(void* const* d_in, const int* in_sizes, int n_in,
                              void* d_out, int out_size) {
    const float* x_in = (const float*)d_in[0];
    const int*   src  = (const int*)d_in[1];
    const int*   dst  = (const int*)d_in[2];
    const int*   gid  = (const int*)d_in[3];
    const float* p1   = (const float*)d_in[4];
    const float* p2   = (const float*)d_in[5];
    const float* p3   = (const float*)d_in[6];
    const float* W1s = (const float*)d_in[7],  *W1d = (const float*)d_in[8];
    const float* a1  = (const float*)d_in[9],  *b1  = (const float*)d_in[10];
    const float* W2s = (const float*)d_in[11], *W2d = (const float*)d_in[12];
    const float* a2  = (const float*)d_in[13], *b2  = (const float*)d_in[14];
    const float* W3s = (const float*)d_in[15], *W3d = (const float*)d_in[16];
    const float* a3  = (const float*)d_in[17], *b3  = (const float*)d_in[18];
    const float* Wex = (const float*)d_in[19], *bex = (const float*)d_in[20];
    const float* Wpat= (const float*)d_in[21], *bpat= (const float*)d_in[22];
    const float* Wc1 = (const float*)d_in[23], *bc1 = (const float*)d_in[24];
    const float* Wc2 = (const float*)d_in[25], *bc2 = (const float*)d_in[26];
    const float* Wc3 = (const float*)d_in[27], *bc3 = (const float*)d_in[28];

    cudaFuncSetAttribute(gemm_mma_kernel, cudaFuncAttributeMaxDynamicSharedMemorySize, GEMM_SMEM);

    dim3 gemm_grid((NN + 127) / 128, 3);       // (391, 3)
    int  node_blocks = (NN * 32 + 255) / 256;  // 6250

    // CSR build + pool zero (independent of layer pipeline start)
    zero_deg_kernel<<<(NN + 255) / 256, 256>>>();
    hist_kernel<<<(EE + 255) / 256, 256>>>(dst);
    scan_kernel<<<1, 1024>>>();
    scatter_kernel<<<(EE + 255) / 256, 256>>>(src, dst);
    pool_zero_kernel<<<17, 256>>>();

    // ---- Layer 1 (K = 128)
    convert_x_kernel<<<(NN * F_IN / 4 + 255) / 256, 256>>>(x_in);
    convert_w_kernel<<<(F_IN * 384 + 255) / 256, 256>>>(W1s, W1d, F_IN);
    gemm_mma_kernel<<<gemm_grid, 256, GEMM_SMEM>>>(F_IN);
    gat_node_kernel<<<node_blocks, 256>>>(a1, b1, 0, gid);

    // ---- Layer 2 (K = 192)
    convert_w_kernel<<<(HD * 384 + 255) / 256, 256>>>(W2s, W2d, HD);
    gemm_mma_kernel<<<gemm_grid, 256, GEMM_SMEM>>>(HD);
    gat_node_kernel<<<node_blocks, 256>>>(a2, b2, 0, gid);

    // ---- Layer 3 (pooling fused)
    convert_w_kernel<<<(HD * 384 + 255) / 256, 256>>>(W3s, W3d, HD);
    gemm_mma_kernel<<<gemm_grid, 256, GEMM_SMEM>>>(HD);
    gat_node_kernel<<<node_blocks, 256>>>(a3, b3, 1, gid);

    // ---- head
    head_kernel<<<1, 256>>>(p1, p2, p3, Wex, bex, Wpat, bpat,
                            Wc1, bc1, Wc2, bc2, Wc3, bc3, (float*)d_out);
}

// round 6
// speedup vs baseline: 2.3951x; 1.0143x over previous
#include <cuda_runtime.h>
#include <cuda_bf16.h>
#include <math.h>
#include <stdint.h>

#define NN   50000
#define EE   400000
#define F_IN 128
#define HH   3
#define DD   64
#define HD   192
#define GG   64
#define PP   64
#define NEG_GAT 0.2f
#define NEG  0.01f

// ---------------- device scratch ----------------
__device__ __align__(16) float g_fs[(size_t)NN * HD];
__device__ __align__(16) float g_fd[(size_t)NN * HD];
__device__ __align__(16) __nv_bfloat16 g_xh[(size_t)NN * HD];   // activation hi (bf16 split)
__device__ __align__(16) __nv_bfloat16 g_xl[(size_t)NN * HD];   // activation lo
__device__ __align__(16) __nv_bfloat16 g_wh[(size_t)HD * 384];  // [K][384] weight hi
__device__ __align__(16) __nv_bfloat16 g_wl[(size_t)HD * 384];  // weight lo
__device__ int g_deg[NN];
__device__ int g_rowptr[NN + 1];
__device__ int g_cur[NN];
__device__ int g_esrc[EE];
__device__ float g_pool[GG * DD];
__device__ float g_cnt[GG];

// ---------------- PTX helpers ----------------
__device__ __forceinline__ uint32_t cvta_shared_u32(const void* p) {
    uint32_t a;
    asm("{ .reg .u64 t; cvta.to.shared.u64 t, %1; cvt.u32.u64 %0, t; }" : "=r"(a) : "l"(p));
    return a;
}
__device__ __forceinline__ void cpasync16(uint32_t smem, const void* g, int srcsize) {
    asm volatile("cp.async.cg.shared.global [%0], [%1], 16, %2;"
                 :: "r"(smem), "l"(g), "r"(srcsize) : "memory");
}
__device__ __forceinline__ void cp_commit() {
    asm volatile("cp.async.commit_group;" ::: "memory");
}
template <int N> __device__ __forceinline__ void cp_wait() {
    asm volatile("cp.async.wait_group %0;" :: "n"(N) : "memory");
}
__device__ __forceinline__ void ldsm4(uint32_t* r, uint32_t addr) {
    asm volatile("ldmatrix.sync.aligned.m8n8.x4.shared.b16 {%0,%1,%2,%3}, [%4];"
                 : "=r"(r[0]), "=r"(r[1]), "=r"(r[2]), "=r"(r[3]) : "r"(addr));
}
__device__ __forceinline__ void ldsm4t(uint32_t* r, uint32_t addr) {
    asm volatile("ldmatrix.sync.aligned.m8n8.x4.trans.shared.b16 {%0,%1,%2,%3}, [%4];"
                 : "=r"(r[0]), "=r"(r[1]), "=r"(r[2]), "=r"(r[3]) : "r"(addr));
}
__device__ __forceinline__ void mma16816(float* c, const uint32_t* a, const uint32_t* b) {
    asm volatile("mma.sync.aligned.m16n8k16.row.col.f32.bf16.bf16.f32 "
                 "{%0,%1,%2,%3}, {%4,%5,%6,%7}, {%8,%9}, {%0,%1,%2,%3};"
                 : "+f"(c[0]), "+f"(c[1]), "+f"(c[2]), "+f"(c[3])
                 : "r"(a[0]), "r"(a[1]), "r"(a[2]), "r"(a[3]), "r"(b[0]), "r"(b[1]));
}
__device__ __forceinline__ void store_split(float2 v, __nv_bfloat162* h, __nv_bfloat162* l) {
    __nv_bfloat16 hx = __float2bfloat16(v.x);
    __nv_bfloat16 hy = __float2bfloat16(v.y);
    __nv_bfloat162 hv; hv.x = hx; hv.y = hy;
    __nv_bfloat162 lv;
    lv.x = __float2bfloat16(v.x - __bfloat162float(hx));
    lv.y = __float2bfloat16(v.y - __bfloat162float(hy));
    *h = hv; *l = lv;
}

// ---------------- CSR build (graph static across layers) ----------------
__global__ void zero_deg_kernel() {
    int i = blockIdx.x * blockDim.x + threadIdx.x;
    if (i < NN) g_deg[i] = 0;
}
__global__ void hist_kernel(const int* __restrict__ dst) {
    int e = blockIdx.x * blockDim.x + threadIdx.x;
    if (e < EE) atomicAdd(&g_deg[dst[e]], 1);
}
__global__ void scan_kernel() {
    __shared__ int sp[1024];
    int tid = threadIdx.x;
    int start = tid * 49;
    int end = start + 49; if (end > NN) end = NN;
    int loc = 0;
    for (int i = start; i < end; i++) loc += g_deg[i];
    sp[tid] = loc;
    __syncthreads();
    for (int off = 1; off < 1024; off <<= 1) {
        int v = (tid >= off) ? sp[tid - off] : 0;
        __syncthreads();
        sp[tid] += v;
        __syncthreads();
    }
    int run = sp[tid] - loc;
    for (int i = start; i < end; i++) {
        g_rowptr[i] = run; g_cur[i] = run; run += g_deg[i];
    }
    if (tid == 1023) g_rowptr[NN] = run;
}
__global__ void scatter_kernel(const int* __restrict__ src, const int* __restrict__ dst) {
    int e = blockIdx.x * blockDim.x + threadIdx.x;
    if (e >= EE) return;
    int pos = atomicAdd(&g_cur[dst[e]], 1);
    g_esrc[pos] = src[e];
}

// ---------------- operand conversions ----------------
__global__ void convert_x_kernel(const float* __restrict__ x) {
    int idx = blockIdx.x * blockDim.x + threadIdx.x;
    if (idx >= NN * F_IN / 4) return;
    float4 v = reinterpret_cast<const float4*>(x)[idx];
    __nv_bfloat162 h0, l0, h1, l1;
    store_split(make_float2(v.x, v.y), &h0, &l0);
    store_split(make_float2(v.z, v.w), &h1, &l1);
    __nv_bfloat162* oh = reinterpret_cast<__nv_bfloat162*>(g_xh);
    __nv_bfloat162* ol = reinterpret_cast<__nv_bfloat162*>(g_xl);
    oh[idx * 2] = h0; oh[idx * 2 + 1] = h1;
    ol[idx * 2] = l0; ol[idx * 2 + 1] = l1;
}
__global__ void convert_w_kernel(const float* __restrict__ Ws, const float* __restrict__ Wd, int K) {
    int idx = blockIdx.x * blockDim.x + threadIdx.x;
    if (idx >= K * 384) return;
    int k = idx / 384, n = idx % 384;
    float w = (n < HD) ? Ws[(size_t)k * HD + n] : Wd[(size_t)k * HD + n - HD];
    __nv_bfloat16 h = __float2bfloat16(w);
    g_wh[idx] = h;
    g_wl[idx] = __float2bfloat16(w - __bfloat162float(h));
}

// ---------------- mma.sync split-bf16 GEMM: [g_fs|g_fd] = X @ [Ws|Wd] ------------
#define STAGE_BYTES 37888
#define SA_LO 10240
#define SB_HI 20480
#define GEMM_SMEM (2 * STAGE_BYTES)

__global__ __launch_bounds__(256) void gemm_mma_kernel(int K) {
    extern __shared__ char smdyn[];
    uint32_t smb = cvta_shared_u32(smdyn);
    int tid = threadIdx.x, lane = tid & 31;
    int wid = tid >> 5, wr = wid & 1, wc = wid >> 1;
    int row0 = blockIdx.x * 128, col0 = blockIdx.y * 128;
    int nk = K >> 5;

    float c[4][4][4];
#pragma unroll
    for (int i = 0; i < 4; i++)
#pragma unroll
        for (int j = 0; j < 4; j++)
#pragma unroll
            for (int k = 0; k < 4; k++) c[i][j][k] = 0.f;

    auto issue = [&](int t, int st) {
        int k0 = t << 5;
        uint32_t sb = smb + st * STAGE_BYTES;
#pragma unroll
        for (int h = 0; h < 2; h++) {
            int cc = tid + h * 256;
            int ar = cc >> 2, acg = (cc & 3) << 3;
            int grow = row0 + ar;
            int ok = (grow < NN) ? 16 : 0;
            const __nv_bfloat16* ph = ok ? (g_xh + (size_t)grow * K + k0 + acg) : g_xh;
            const __nv_bfloat16* pl = ok ? (g_xl + (size_t)grow * K + k0 + acg) : g_xl;
            uint32_t da = sb + ar * 80 + (acg << 1);
            cpasync16(da, ph, ok);
            cpasync16(da + SA_LO, pl, ok);
            int br = cc >> 4, bcg = (cc & 15) << 3;
            const __nv_bfloat16* qh = g_wh + (size_t)(k0 + br) * 384 + col0 + bcg;
            const __nv_bfloat16* ql = g_wl + (size_t)(k0 + br) * 384 + col0 + bcg;
            uint32_t db = sb + SB_HI + br * 272 + (bcg << 1);
            cpasync16(db, qh, 16);
            cpasync16(db + 8704, ql, 16);
        }
        cp_commit();
    };

    issue(0, 0);

    const int arow = wr * 64 + (lane & 15);
    const int acol = (lane >> 4) << 3;
    const int krow = (lane & 15);
    const int ncll = wc * 32 + ((lane >> 4) << 3);

    for (int t = 0; t < nk; t++) {
        int st = t & 1;
        if (t + 1 < nk) { issue(t + 1, st ^ 1); cp_wait<1>(); }
        else            { cp_wait<0>(); }
        __syncthreads();
        uint32_t sb = smb + st * STAGE_BYTES;
#pragma unroll
        for (int ks = 0; ks < 2; ks++) {
            uint32_t Ah[4][4], Al[4][4], B[4][2];
#pragma unroll
            for (int mt = 0; mt < 4; mt++) {
                uint32_t ad = sb + (arow + mt * 16) * 80 + ((ks * 16 + acol) << 1);
                ldsm4(Ah[mt], ad);
                ldsm4(Al[mt], ad + SA_LO);
            }
            uint32_t bk = sb + SB_HI + (ks * 16 + krow) * 272;
#pragma unroll
            for (int np = 0; np < 2; np++) {
                uint32_t r[4];
                ldsm4t(r, bk + ((ncll + np * 16) << 1));
                B[2*np][0] = r[0]; B[2*np][1] = r[1];
                B[2*np+1][0] = r[2]; B[2*np+1][1] = r[3];
            }
#pragma unroll
            for (int mt = 0; mt < 4; mt++)
#pragma unroll
                for (int nt = 0; nt < 4; nt++) mma16816(c[mt][nt], Ah[mt], B[nt]);
#pragma unroll
            for (int mt = 0; mt < 4; mt++)
#pragma unroll
                for (int nt = 0; nt < 4; nt++) mma16816(c[mt][nt], Al[mt], B[nt]);
#pragma unroll
            for (int np = 0; np < 2; np++) {
                uint32_t r[4];
                ldsm4t(r, bk + 8704 + ((ncll + np * 16) << 1));
                B[2*np][0] = r[0]; B[2*np][1] = r[1];
                B[2*np+1][0] = r[2]; B[2*np+1][1] = r[3];
            }
#pragma unroll
            for (int mt = 0; mt < 4; mt++)
#pragma unroll
                for (int nt = 0; nt < 4; nt++) mma16816(c[mt][nt], Ah[mt], B[nt]);
        }
        __syncthreads();
    }

    int gid4 = lane >> 2, tig = lane & 3;
#pragma unroll
    for (int mt = 0; mt < 4; mt++) {
        int rg = row0 + wr * 64 + mt * 16 + gid4;
#pragma unroll
        for (int nt = 0; nt < 4; nt++) {
            int col = col0 + wc * 32 + nt * 8 + tig * 2;
            float* base = (col < HD) ? (g_fs + col) : (g_fd + (col - HD));
            if (rg < NN)
                *reinterpret_cast<float2*>(base + (size_t)rg * HD) =
                    make_float2(c[mt][nt][0], c[mt][nt][1]);
            if (rg + 8 < NN)
                *reinterpret_cast<float2*>(base + (size_t)(rg + 8) * HD) =
                    make_float2(c[mt][nt][2], c[mt][nt][3]);
        }
    }
}

// ---------------- fused single-pass GATv2: one warp per node, 2-edge ILP ----------
__device__ __forceinline__ void edge_logits(
        int s, const float2* __restrict__ /*unused*/, int lane,
        float2 va0, float2 va1, float2 va2,
        float2 vd0, float2 vd1, float2 vd2,
        float2& u0, float2& u1, float2& u2,
        float& l0, float& l1, float& l2) {
    const float2* fs2 = reinterpret_cast<const float2*>(g_fs + (size_t)s * HD);
    u0 = fs2[lane]; u1 = fs2[lane + 32]; u2 = fs2[lane + 64];
    float x, y;
    x = u0.x + vd0.x; x = x > 0.f ? x : NEG_GAT * x;
    y = u0.y + vd0.y; y = y > 0.f ? y : NEG_GAT * y;
    l0 = x * va0.x + y * va0.y;
    x = u1.x + vd1.x; x = x > 0.f ? x : NEG_GAT * x;
    y = u1.y + vd1.y; y = y > 0.f ? y : NEG_GAT * y;
    l1 = x * va1.x + y * va1.y;
    x = u2.x + vd2.x; x = x > 0.f ? x : NEG_GAT * x;
    y = u2.y + vd2.y; y = y > 0.f ? y : NEG_GAT * y;
    l2 = x * va2.x + y * va2.y;
}

__global__ void gat_node_kernel(const float* __restrict__ attn,
                                const float* __restrict__ bias,
                                int do_pool, const int* __restrict__ gid) {
    int gw = (blockIdx.x * blockDim.x + threadIdx.x) >> 5;
    if (gw >= NN) return;
    int lane = threadIdx.x & 31;
    int n = gw;
    int p0 = g_rowptr[n], p1 = g_rowptr[n + 1];

    const float2* a2  = reinterpret_cast<const float2*>(attn);
    const float2* fd2 = reinterpret_cast<const float2*>(g_fd + (size_t)n * HD);
    float2 va0 = a2[lane], va1 = a2[lane + 32], va2 = a2[lane + 64];
    float2 vd0 = fd2[lane], vd1 = fd2[lane + 32], vd2 = fd2[lane + 64];

    float den0 = 0.f, den1 = 0.f, den2 = 0.f;
    float2 acc0 = make_float2(0.f, 0.f), acc1 = acc0, acc2 = acc0;

    int p = p0;
    for (; p + 1 < p1; p += 2) {
        int sA = g_esrc[p], sB = g_esrc[p + 1];
        float2 uA0, uA1, uA2, uB0, uB1, uB2;
        float lA0, lA1, lA2, lB0, lB1, lB2;
        edge_logits(sA, nullptr, lane, va0, va1, va2, vd0, vd1, vd2, uA0, uA1, uA2, lA0, lA1, lA2);
        edge_logits(sB, nullptr, lane, va0, va1, va2, vd0, vd1, vd2, uB0, uB1, uB2, lB0, lB1, lB2);
#pragma unroll
        for (int o = 16; o; o >>= 1) {
            lA0 += __shfl_xor_sync(0xffffffffu, lA0, o);
            lB0 += __shfl_xor_sync(0xffffffffu, lB0, o);
            lA1 += __shfl_xor_sync(0xffffffffu, lA1, o);
            lB1 += __shfl_xor_sync(0xffffffffu, lB1, o);
            lA2 += __shfl_xor_sync(0xffffffffu, lA2, o);
            lB2 += __shfl_xor_sync(0xffffffffu, lB2, o);
        }
        float eA0 = expf(lA0), eA1 = expf(lA1), eA2 = expf(lA2);
        float eB0 = expf(lB0), eB1 = expf(lB1), eB2 = expf(lB2);
        den0 += eA0 + eB0; den1 += eA1 + eB1; den2 += eA2 + eB2;
        acc0.x += eA0 * uA0.x + eB0 * uB0.x; acc0.y += eA0 * uA0.y + eB0 * uB0.y;
        acc1.x += eA1 * uA1.x + eB1 * uB1.x; acc1.y += eA1 * uA1.y + eB1 * uB1.y;
        acc2.x += eA2 * uA2.x + eB2 * uB2.x; acc2.y += eA2 * uA2.y + eB2 * uB2.y;
    }
    if (p < p1) {
        int s = g_esrc[p];
        float2 u0, u1, u2;
        float l0, l1, l2;
        edge_logits(s, nullptr, lane, va0, va1, va2, vd0, vd1, vd2, u0, u1, u2, l0, l1, l2);
#pragma unroll
        for (int o = 16; o; o >>= 1) {
            l0 += __shfl_xor_sync(0xffffffffu, l0, o);
            l1 += __shfl_xor_sync(0xffffffffu, l1, o);
            l2 += __shfl_xor_sync(0xffffffffu, l2, o);
        }
        float e0 = expf(l0), e1 = expf(l1), e2 = expf(l2);
        den0 += e0; den1 += e1; den2 += e2;
        acc0.x += e0 * u0.x; acc0.y += e0 * u0.y;
        acc1.x += e1 * u1.x; acc1.y += e1 * u1.y;
        acc2.x += e2 * u2.x; acc2.y += e2 * u2.y;
    }

    float i0 = 1.f / fmaxf(den0, 1e-9f);
    float i1 = 1.f / fmaxf(den1, 1e-9f);
    float i2 = 1.f / fmaxf(den2, 1e-9f);

    const float2* b2 = reinterpret_cast<const float2*>(bias);
    float2 w0 = b2[lane], w1 = b2[lane + 32], w2 = b2[lane + 64];
    float2 o0 = make_float2(acc0.x * i0 + w0.x, acc0.y * i0 + w0.y);
    float2 o1 = make_float2(acc1.x * i1 + w1.x, acc1.y * i1 + w1.y);
    float2 o2 = make_float2(acc2.x * i2 + w2.x, acc2.y * i2 + w2.y);

    if (!do_pool) {
        __nv_bfloat162* oh = reinterpret_cast<__nv_bfloat162*>(g_xh + (size_t)n * HD);
        __nv_bfloat162* ol = reinterpret_cast<__nv_bfloat162*>(g_xl + (size_t)n * HD);
        store_split(o0, &oh[lane],      &ol[lane]);
        store_split(o1, &oh[lane + 32], &ol[lane + 32]);
        store_split(o2, &oh[lane + 64], &ol[lane + 64]);
    } else {
        int g = gid[n];
        float vx = (o0.x + o1.x + o2.x) * (1.f / 3.f);
        float vy = (o0.y + o1.y + o2.y) * (1.f / 3.f);
        atomicAdd(&g_pool[g * DD + 2 * lane], vx);
        atomicAdd(&g_pool[g * DD + 2 * lane + 1], vy);
        if (lane == 0) atomicAdd(&g_cnt[g], 1.f);
    }
}

// ---------------- pool zero ----------------
__global__ void pool_zero_kernel() {
    int i = blockIdx.x * blockDim.x + threadIdx.x;
    if (i < GG * DD) g_pool[i] = 0.f;
    if (i < GG) g_cnt[i] = 0.f;
}

// ---------------- pattern branch + classifier head ----------------
__global__ void head_kernel(const float* __restrict__ p1, const float* __restrict__ p2,
                            const float* __restrict__ p3,
                            const float* __restrict__ Wex, const float* __restrict__ bex,
                            const float* __restrict__ Wpat, const float* __restrict__ bpat,
                            const float* __restrict__ Wc1, const float* __restrict__ bc1,
                            const float* __restrict__ Wc2, const float* __restrict__ bc2,
                            const float* __restrict__ Wc3, const float* __restrict__ bc3,
                            float* __restrict__ outp) {
    __shared__ float s_px[GG * 96];
    __shared__ float s_pat[GG * 64];
    int tid = threadIdx.x;

    for (int idx = tid; idx < GG * 96; idx += 256) {
        int g = idx / 96, j = idx % 96;
        const float* p = (j < 32) ? p1 : (j < 64 ? p2 : p3);
        int jj = j & 31;
        float s = bex[jj];
        for (int k = 0; k < PP; k++) s += p[g * PP + k] * Wex[k * 32 + jj];
        s_px[idx] = s;
    }
    __syncthreads();
    for (int idx = tid; idx < GG * 64; idx += 256) {
        int g = idx >> 6, j = idx & 63;
        float s = bpat[j];
        for (int k = 0; k < 96; k++) s += s_px[g * 96 + k] * Wpat[k * 64 + j];
        s_pat[idx] = s > 0.f ? s : NEG * s;
    }
    __syncthreads();
    for (int idx = tid; idx < GG * 64; idx += 256) {
        int g = idx >> 6, j = idx & 63;
        float s = bc1[j];
        float inv = 1.f / fmaxf(g_cnt[g], 1.f);
        for (int k = 0; k < 64; k++) s += (g_pool[g * 64 + k] * inv) * Wc1[k * 64 + j];
        for (int k = 0; k < 64; k++) s += s_pat[g * 64 + k] * Wc1[(64 + k) * 64 + j];
        s_px[idx] = s > 0.f ? s : NEG * s;
    }
    __syncthreads();
    for (int idx = tid; idx < GG * 32; idx += 256) {
        int g = idx >> 5, j = idx & 31;
        float s = bc2[j];
        for (int k = 0; k < 64; k++) s += s_px[g * 64 + k] * Wc2[k * 32 + j];
        s_px[4096 + idx] = s > 0.f ? s : NEG * s;
    }
    __syncthreads();
    for (int idx = tid; idx < GG * 2; idx += 256) {
        int g = idx >> 1, j = idx & 1;
        float s = bc3[j];
        for (int k = 0; k < 32; k++) s += s_px[4096 + g * 32 + k] * Wc3[k * 2 + j];
        outp[idx] = s;
    }
}

// ---------------- launcher ----------------
extern "C" void kernel_launch(void* const* d_in, const int* in_sizes, int n_in,
                              void* d_out, int out_size) {
    const float* x_in = (const float*)d_in[0];
    const int*   src  = (const int*)d_in[1];
    const int*   dst  = (const int*)d_in[2];
    const int*   gid  = (const int*)d_in[3];
    const float* p1   = (const float*)d_in[4];
    const float* p2   = (const float*)d_in[5];
    const float* p3   = (const float*)d_in[6];
    const float* W1s = (const float*)d_in[7],  *W1d = (const float*)d_in[8];
    const float* a1  = (const float*)d_in[9],  *b1  = (const float*)d_in[10];
    const float* W2s = (const float*)d_in[11], *W2d = (const float*)d_in[12];
    const float* a2  = (const float*)d_in[13], *b2  = (const float*)d_in[14];
    const float* W3s = (const float*)d_in[15], *W3d = (const float*)d_in[16];
    const float* a3  = (const float*)d_in[17], *b3  = (const float*)d_in[18];
    const float* Wex = (const float*)d_in[19], *bex = (const float*)d_in[20];
    const float* Wpat= (const float*)d_in[21], *bpat= (const float*)d_in[22];
    const float* Wc1 = (const float*)d_in[23], *bc1 = (const float*)d_in[24];
    const float* Wc2 = (const float*)d_in[25], *bc2 = (const float*)d_in[26];
    const float* Wc3 = (const float*)d_in[27], *bc3 = (const float*)d_in[28];

    cudaFuncSetAttribute(gemm_mma_kernel, cudaFuncAttributeMaxDynamicSharedMemorySize, GEMM_SMEM);

    dim3 gemm_grid((NN + 127) / 128, 3);       // (391, 3)
    int  node_blocks = (NN * 32 + 255) / 256;  // 6250

    // Launch order chosen so the profiled slot (4th launch) lands on gemm_mma.
    pool_zero_kernel<<<17, 256>>>();                                     // 1
    convert_x_kernel<<<(NN * F_IN / 4 + 255) / 256, 256>>>(x_in);        // 2
    convert_w_kernel<<<(F_IN * 384 + 255) / 256, 256>>>(W1s, W1d, F_IN); // 3
    gemm_mma_kernel<<<gemm_grid, 256, GEMM_SMEM>>>(F_IN);                // 4 <- ncu slot

    // CSR build (needed only by gat kernels)
    zero_deg_kernel<<<(NN + 255) / 256, 256>>>();                        // 5
    hist_kernel<<<(EE + 255) / 256, 256>>>(dst);                         // 6
    scan_kernel<<<1, 1024>>>();                                          // 7
    scatter_kernel<<<(EE + 255) / 256, 256>>>(src, dst);                 // 8

    gat_node_kernel<<<node_blocks, 256>>>(a1, b1, 0, gid);               // 9

    // ---- Layer 2 (K = 192)
    convert_w_kernel<<<(HD * 384 + 255) / 256, 256>>>(W2s, W2d, HD);
    gemm_mma_kernel<<<gemm_grid, 256, GEMM_SMEM>>>(HD);
    gat_node_kernel<<<node_blocks, 256>>>(a2, b2, 0, gid);

    // ---- Layer 3 (pooling fused)
    convert_w_kernel<<<(HD * 384 + 255) / 256, 256>>>(W3s, W3d, HD);
    gemm_mma_kernel<<<gemm_grid, 256, GEMM_SMEM>>>(HD);
    gat_node_kernel<<<node_blocks, 256>>>(a3, b3, 1, gid);

    // ---- head
    head_kernel<<<1, 256>>>(p1, p2, p3, Wex, bex, Wpat, bpat,
                            Wc1, bc1, Wc2, bc2, Wc3, bc3, (float*)d_out);
}